// round 10
// baseline (speedup 1.0000x reference)
#include <cuda_runtime.h>
#include <cuda_bf16.h>
#include <stdint.h>
#include <math.h>

#define NB 4
#define TT 2048
#define TI 2048
#define HH 1024
#define UU 4096

typedef __nv_bfloat16 bf16;

// ---------------------------------------------------------------------------
// Scratch (allocation-free: __device__ globals)
// ---------------------------------------------------------------------------
__device__ bf16 g_te_h[(size_t)NB*TT*HH];
__device__ bf16 g_te_l[(size_t)NB*TT*HH];
__device__ bf16 g_ie_h[(size_t)NB*TI*HH];
__device__ bf16 g_ie_l[(size_t)NB*TI*HH];
__device__ bf16 g_ieT_h[(size_t)NB*HH*TI];
__device__ bf16 g_ieT_l[(size_t)NB*HH*TI];
__device__ float g_logits[(size_t)NB*TT*TI];
__device__ bf16 g_p_h[(size_t)NB*TT*TI];
__device__ bf16 g_p_l[(size_t)NB*TT*TI];
__device__ bf16 g_at_h[(size_t)NB*TT*HH];
__device__ bf16 g_at_l[(size_t)NB*TT*HH];
__device__ bf16 g_hb_h[(size_t)NB*TT*UU];
__device__ bf16 g_hb_l[(size_t)NB*TT*UU];
__device__ bf16 g_cw_h[(size_t)UU*3*HH];
__device__ bf16 g_cw_l[(size_t)UU*3*HH];
__device__ bf16 g_dw_h[(size_t)HH*UU];
__device__ bf16 g_dw_l[(size_t)HH*UU];

// ---------------------------------------------------------------------------
// Helpers
// ---------------------------------------------------------------------------
__device__ __forceinline__ uint32_t cvta_smem(const void* p) {
    uint32_t a;
    asm("{ .reg .u64 t; cvta.to.shared.u64 t, %1; cvt.u32.u64 %0, t; }"
        : "=r"(a) : "l"(p));
    return a;
}
__device__ __forceinline__ void bsplit(float v, bf16& h, bf16& l) {
    h = __float2bfloat16(v);
    l = __float2bfloat16(v - __bfloat162float(h));
}
__device__ __forceinline__ void cpa16(uint32_t d, const void* s) {
    asm volatile("cp.async.cg.shared.global [%0], [%1], 16;" :: "r"(d), "l"(s));
}
__device__ __forceinline__ void cpa16z(uint32_t d, const void* s, unsigned sz) {
    asm volatile("cp.async.cg.shared.global [%0], [%1], 16, %2;"
                 :: "r"(d), "l"(s), "r"(sz));
}
__device__ __forceinline__ void cpa_commit() {
    asm volatile("cp.async.commit_group;" ::: "memory");
}
template <int N>
__device__ __forceinline__ void cpa_wait() {
    asm volatile("cp.async.wait_group %0;" :: "n"(N) : "memory");
}
// SW64 swizzle: bits[4:5] ^= bits[7:8] (row stride 64B, conflict-free ldmatrix)
__device__ __forceinline__ uint32_t sw64(uint32_t o) {
    return o ^ ((o >> 3) & 0x30);
}

#define LDM4(f, a) \
    asm volatile("ldmatrix.sync.aligned.m8n8.x4.shared.b16 {%0,%1,%2,%3}, [%4];" \
        : "=r"((f)[0]), "=r"((f)[1]), "=r"((f)[2]), "=r"((f)[3]) : "r"(a))
#define MMA16816(d, a, b) \
    asm volatile("mma.sync.aligned.m16n8k16.row.col.f32.bf16.bf16.f32 " \
        "{%0,%1,%2,%3}, {%4,%5,%6,%7}, {%8,%9}, {%0,%1,%2,%3};" \
        : "+f"((d)[0]), "+f"((d)[1]), "+f"((d)[2]), "+f"((d)[3]) \
        : "r"((a)[0]), "r"((a)[1]), "r"((a)[2]), "r"((a)[3]), \
          "r"((b)[0]), "r"((b)[1]))

// ---------------------------------------------------------------------------
// Embedding gather + scale + bf16 hi/lo split
// ---------------------------------------------------------------------------
__global__ void gather_split(const int* __restrict__ idx, const float* __restrict__ emb,
                             bf16* __restrict__ oh, bf16* __restrict__ ol,
                             int n_tok, float scale) {
    int i = blockIdx.x * 256 + threadIdx.x;
    if (i >= n_tok * 256) return;
    int tok = i >> 8, h4 = i & 255;
    float4 v = ((const float4*)emb)[(size_t)idx[tok] * 256 + h4];
    float f[4] = {v.x * scale, v.y * scale, v.z * scale, v.w * scale};
    bf16 h[4], l[4];
    #pragma unroll
    for (int k = 0; k < 4; ++k) bsplit(f[k], h[k], l[k]);
    size_t o = (size_t)tok * HH + h4 * 4;
    __nv_bfloat162 a, b;
    a.x = h[0]; a.y = h[1]; b.x = h[2]; b.y = h[3];
    *(__nv_bfloat162*)(oh + o) = a; *(__nv_bfloat162*)(oh + o + 2) = b;
    a.x = l[0]; a.y = l[1]; b.x = l[2]; b.y = l[3];
    *(__nv_bfloat162*)(ol + o) = a; *(__nv_bfloat162*)(ol + o + 2) = b;
}

// ---------------------------------------------------------------------------
// bf16 transpose [R,C] -> [C,R]; z selects (batch, hi/lo plane)
// ---------------------------------------------------------------------------
__global__ void transpose_b2(const bf16* __restrict__ in0, bf16* __restrict__ out0,
                             const bf16* __restrict__ in1, bf16* __restrict__ out1,
                             int R, int C, int zsplit) {
    __shared__ bf16 t[32][33];
    int zz = blockIdx.z;
    const bf16* in;
    bf16* out;
    if (zz < zsplit) { in = in0 + (size_t)zz * R * C; out = out0 + (size_t)zz * R * C; }
    else { zz -= zsplit; in = in1 + (size_t)zz * R * C; out = out1 + (size_t)zz * R * C; }
    int c0 = blockIdx.x * 32, r0 = blockIdx.y * 32;
    for (int i = threadIdx.y; i < 32; i += 8)
        t[i][threadIdx.x] = in[(size_t)(r0 + i) * C + c0 + threadIdx.x];
    __syncthreads();
    for (int i = threadIdx.y; i < 32; i += 8)
        out[(size_t)(c0 + i) * R + r0 + threadIdx.x] = t[threadIdx.x][i];
}

// fp32 weight transpose [R,C] -> bf16 hi/lo [C,R]
__global__ void transpose_split_w(const float* __restrict__ in,
                                  bf16* __restrict__ oh, bf16* __restrict__ ol,
                                  int R, int C) {
    __shared__ float t[32][33];
    int c0 = blockIdx.x * 32, r0 = blockIdx.y * 32;
    for (int i = threadIdx.y; i < 32; i += 8)
        t[i][threadIdx.x] = in[(size_t)(r0 + i) * C + c0 + threadIdx.x];
    __syncthreads();
    for (int i = threadIdx.y; i < 32; i += 8) {
        bf16 h, l;
        bsplit(t[threadIdx.x][i], h, l);
        size_t o = (size_t)(c0 + i) * R + r0 + threadIdx.x;
        oh[o] = h; ol[o] = l;
    }
}

// ---------------------------------------------------------------------------
// Softmax over TI cols, writes bf16 hi/lo probabilities
// ---------------------------------------------------------------------------
__global__ void softmax_split(const float* __restrict__ logits,
                              bf16* __restrict__ ph_, bf16* __restrict__ pl_) {
    __shared__ float red[256];
    const int tid = threadIdx.x;
    const float4* p = (const float4*)(logits + (size_t)blockIdx.x * TI);
    float4 v0 = p[tid];
    float4 v1 = p[tid + 256];

    float m = fmaxf(fmaxf(fmaxf(v0.x, v0.y), fmaxf(v0.z, v0.w)),
                    fmaxf(fmaxf(v1.x, v1.y), fmaxf(v1.z, v1.w)));
    red[tid] = m;
    __syncthreads();
    #pragma unroll
    for (int s = 128; s > 0; s >>= 1) {
        if (tid < s) red[tid] = fmaxf(red[tid], red[tid + s]);
        __syncthreads();
    }
    m = red[0];
    __syncthreads();

    v0.x = expf(v0.x - m); v0.y = expf(v0.y - m);
    v0.z = expf(v0.z - m); v0.w = expf(v0.w - m);
    v1.x = expf(v1.x - m); v1.y = expf(v1.y - m);
    v1.z = expf(v1.z - m); v1.w = expf(v1.w - m);

    red[tid] = v0.x + v0.y + v0.z + v0.w + v1.x + v1.y + v1.z + v1.w;
    __syncthreads();
    #pragma unroll
    for (int s = 128; s > 0; s >>= 1) {
        if (tid < s) red[tid] += red[tid + s];
        __syncthreads();
    }
    float inv = 1.f / red[0];

    size_t base = (size_t)blockIdx.x * TI;
    float f[8] = {v0.x*inv, v0.y*inv, v0.z*inv, v0.w*inv,
                  v1.x*inv, v1.y*inv, v1.z*inv, v1.w*inv};
    #pragma unroll
    for (int g = 0; g < 2; ++g) {
        size_t o = base + (size_t)(tid + g * 256) * 4;
        bf16 h[4], l[4];
        #pragma unroll
        for (int k = 0; k < 4; ++k) bsplit(f[g*4 + k], h[k], l[k]);
        __nv_bfloat162 a, b;
        a.x = h[0]; a.y = h[1]; b.x = h[2]; b.y = h[3];
        *(__nv_bfloat162*)(ph_ + o) = a; *(__nv_bfloat162*)(ph_ + o + 2) = b;
        a.x = l[0]; a.y = l[1]; b.x = l[2]; b.y = l[3];
        *(__nv_bfloat162*)(pl_ + o) = a; *(__nv_bfloat162*)(pl_ + o + 2) = b;
    }
}

// ---------------------------------------------------------------------------
// bf16x3 GEMM via mma.sync: 128x128 CTA tile, 64x32 warp tile, BK=32,
// SW64-swizzled smem, 3-stage cp.async pipeline, 2 CTAs/SM.
// Mainloop: mid-kt barrier — wait/sync sits between ks=0 and ks=1 so the
// tensor pipe drains ks=0's MMAs during the barrier instead of idling.
// ---------------------------------------------------------------------------
#define TILE_T 8192             // 128 rows * 64B (SW64 swizzled, no pad)
#define STAGE_B (4 * TILE_T)    // Ah, Al, Bh, Bl = 32768
#define NSTAGE 3

template <int AMODE, int EPI>
__global__ __launch_bounds__(256, 2)
void mma_gemm(const bf16* __restrict__ Ah_, const bf16* __restrict__ Al_,
              const bf16* __restrict__ Bh_, const bf16* __restrict__ Bl_,
              const float* __restrict__ bias,
              float* __restrict__ Cf, bf16* __restrict__ Ch, bf16* __restrict__ Cl,
              int K, int lda, int ldb, int ldc,
              size_t sA, size_t sB, size_t sC)
{
    extern __shared__ char smem[];
    const uint32_t sbase = cvta_smem(smem);
    const int tid  = threadIdx.x;
    const int lane = tid & 31;
    const int wid  = tid >> 5;
    const int wm   = wid & 1;   // 0..1 -> 64-row slab
    const int wn   = wid >> 1;  // 0..3 -> 32-col slab

    const size_t z = blockIdx.z;
    Ah_ += z * sA; Al_ += z * sA;
    Bh_ += z * sB; Bl_ += z * sB;
    if (Cf) Cf += z * sC;
    if (Ch) { Ch += z * sC; Cl += z * sC; }

    const int bm = blockIdx.y * 128;
    const int bn = blockIdx.x * 128;
    const int KT = K >> 5;

    float acc[4][4][4];
    #pragma unroll
    for (int a = 0; a < 4; ++a)
        #pragma unroll
        for (int b = 0; b < 4; ++b)
            #pragma unroll
            for (int c = 0; c < 4; ++c) acc[a][b][c] = 0.f;

    // ---- stage loader: per tile 128 rows x 4 x 16B chunks, SW64 swizzled
    auto load_stage = [&](int slot, int kt) {
        const int k0 = kt * 32;
        const uint32_t sb = sbase + slot * STAGE_B;
        #pragma unroll
        for (int half = 0; half < 2; ++half) {
            const int idx = tid + half * 256;
            const int r = idx >> 2;
            const int c = idx & 3;
            const uint32_t so = sw64((uint32_t)(r * 64 + c * 16));
            // A hi/lo
            if (AMODE == 0) {
                cpa16(sb + so,          Ah_ + (size_t)(bm + r) * lda + k0 + c * 8);
                cpa16(sb + TILE_T + so, Al_ + (size_t)(bm + r) * lda + k0 + c * 8);
            } else {
                const int tap = k0 >> 10;
                const int ccol = (k0 & 1023) + c * 8;
                const int m = bm + r;
                const int b = m >> 11;
                const int t = (m & 2047) + tap - 1;
                const unsigned ok = ((unsigned)t < 2048u) ? 16u : 0u;
                const size_t o = ((size_t)b * 2048 + (ok ? t : 0)) * 1024 + ccol;
                cpa16z(sb + so,          Ah_ + o, ok);
                cpa16z(sb + TILE_T + so, Al_ + o, ok);
            }
            // B hi/lo
            cpa16(sb + 2 * TILE_T + so, Bh_ + (size_t)(bn + r) * ldb + k0 + c * 8);
            cpa16(sb + 3 * TILE_T + so, Bl_ + (size_t)(bn + r) * ldb + k0 + c * 8);
        }
        cpa_commit();
    };

    // ---- one ks half-step (16 K-values) of tile kt in slot sb
    auto compute_ks = [&](uint32_t sb, int ks) {
        const uint32_t sbB = sb + 2 * TILE_T;
        uint32_t Ahf[4][4], Alf[4][4];
        const int arow  = wm * 64 + (lane & 15);
        const int ahalf = lane >> 4;
        #pragma unroll
        for (int mf = 0; mf < 4; ++mf) {
            const uint32_t ao = sw64((uint32_t)((arow + mf * 16) * 64
                              + (ks * 2 + ahalf) * 16));
            LDM4(Ahf[mf], sb + ao);
            LDM4(Alf[mf], sb + TILE_T + ao);
        }
        const int bmat = lane >> 3;           // 0..3
        const int brow0 = wn * 32 + (lane & 7) + (bmat >> 1) * 8;
        const int bko = (ks * 2 + (bmat & 1)) * 16;
        #pragma unroll
        for (int np = 0; np < 2; ++np) {
            uint32_t Bhf[4], Blf[4];
            const uint32_t bo = sw64((uint32_t)((brow0 + np * 16) * 64 + bko));
            LDM4(Bhf, sbB + bo);
            LDM4(Blf, sbB + TILE_T + bo);
            // term-major across both n-subtiles: same-acc reuse = 8 MMAs
            #pragma unroll
            for (int sub = 0; sub < 2; ++sub)
                #pragma unroll
                for (int mf = 0; mf < 4; ++mf)
                    MMA16816(acc[mf][np * 2 + sub], Ahf[mf], &Bhf[sub * 2]);
            #pragma unroll
            for (int sub = 0; sub < 2; ++sub)
                #pragma unroll
                for (int mf = 0; mf < 4; ++mf)
                    MMA16816(acc[mf][np * 2 + sub], Ahf[mf], &Blf[sub * 2]);
            #pragma unroll
            for (int sub = 0; sub < 2; ++sub)
                #pragma unroll
                for (int mf = 0; mf < 4; ++mf)
                    MMA16816(acc[mf][np * 2 + sub], Alf[mf], &Bhf[sub * 2]);
        }
    };

    load_stage(0, 0);
    load_stage(1, 1);
    cpa_wait<1>();      // stage 0 landed (stage 1 may still be in flight)
    __syncthreads();    // make stage 0 visible CTA-wide

    for (int kt = 0; kt < KT; ++kt) {
        const uint32_t sb = sbase + (kt % NSTAGE) * STAGE_B;
        // slot kt landed & visible (established by previous iteration / prologue)
        compute_ks(sb, 0);
        // barrier + wait drain UNDER ks=0's in-flight MMAs
        cpa_wait<0>();      // stage kt+1 fully landed (kt+2 not yet issued)
        __syncthreads();    // all warps past slot (kt-1) reads; stage kt+1 visible
        if (kt + 2 < KT) load_stage((kt + 2) % NSTAGE, kt + 2);
        compute_ks(sb, 1);
    }

    // ---- epilogue
    const int mrow = bm + wm * 64 + (lane >> 2);
    const int ncol = bn + wn * 32 + (lane & 3) * 2;
    #pragma unroll
    for (int mf = 0; mf < 4; ++mf) {
        #pragma unroll
        for (int nf = 0; nf < 4; ++nf) {
            const float* a4 = acc[mf][nf];
            #pragma unroll
            for (int h = 0; h < 2; ++h) {
                const int m = mrow + mf * 16 + h * 8;
                const int n = ncol + nf * 8;
                float v0 = a4[h * 2 + 0];
                float v1 = a4[h * 2 + 1];
                if (EPI == 0) {
                    *(float2*)(Cf + (size_t)m * ldc + n) = make_float2(v0, v1);
                } else if (EPI == 3) {
                    *(float2*)(Cf + (size_t)m * ldc + n) =
                        make_float2(v0 + bias[n], v1 + bias[n + 1]);
                } else {
                    if (EPI == 2) {
                        v0 = fmaxf(v0 + bias[n], 0.f);
                        v1 = fmaxf(v1 + bias[n + 1], 0.f);
                    }
                    bf16 h0, l0, h1, l1;
                    bsplit(v0, h0, l0);
                    bsplit(v1, h1, l1);
                    __nv_bfloat162 vh, vl;
                    vh.x = h0; vh.y = h1;
                    vl.x = l0; vl.y = l1;
                    *(__nv_bfloat162*)(Ch + (size_t)m * ldc + n) = vh;
                    *(__nv_bfloat162*)(Cl + (size_t)m * ldc + n) = vl;
                }
            }
        }
    }
}

// ---------------------------------------------------------------------------
extern "C" void kernel_launch(void* const* d_in, const int* in_sizes, int n_in,
                              void* d_out, int out_size) {
    const int*   inputs     = (const int*)d_in[0];
    const int*   targets    = (const int*)d_in[1];
    const float* input_emb  = (const float*)d_in[2];
    const float* target_emb = (const float*)d_in[3];
    const float* conv_w     = (const float*)d_in[4];
    const float* conv_b     = (const float*)d_in[5];
    const float* dense_w    = (const float*)d_in[6];
    const float* dense_b    = (const float*)d_in[7];
    float* out = (float*)d_out;

    bf16 *te_h, *te_l, *ie_h, *ie_l, *ieT_h, *ieT_l, *p_h, *p_l;
    bf16 *at_h, *at_l, *hb_h, *hb_l, *cw_h, *cw_l, *dw_h, *dw_l;
    float* lg;
    cudaGetSymbolAddress((void**)&te_h, g_te_h);
    cudaGetSymbolAddress((void**)&te_l, g_te_l);
    cudaGetSymbolAddress((void**)&ie_h, g_ie_h);
    cudaGetSymbolAddress((void**)&ie_l, g_ie_l);
    cudaGetSymbolAddress((void**)&ieT_h, g_ieT_h);
    cudaGetSymbolAddress((void**)&ieT_l, g_ieT_l);
    cudaGetSymbolAddress((void**)&lg, g_logits);
    cudaGetSymbolAddress((void**)&p_h, g_p_h);
    cudaGetSymbolAddress((void**)&p_l, g_p_l);
    cudaGetSymbolAddress((void**)&at_h, g_at_h);
    cudaGetSymbolAddress((void**)&at_l, g_at_l);
    cudaGetSymbolAddress((void**)&hb_h, g_hb_h);
    cudaGetSymbolAddress((void**)&hb_l, g_hb_l);
    cudaGetSymbolAddress((void**)&cw_h, g_cw_h);
    cudaGetSymbolAddress((void**)&cw_l, g_cw_l);
    cudaGetSymbolAddress((void**)&dw_h, g_dw_h);
    cudaGetSymbolAddress((void**)&dw_l, g_dw_l);

    const int SMEMB = NSTAGE * STAGE_B;  // 98304 -> 2 CTAs/SM
    cudaFuncSetAttribute(mma_gemm<0,0>, cudaFuncAttributeMaxDynamicSharedMemorySize, SMEMB);
    cudaFuncSetAttribute(mma_gemm<0,1>, cudaFuncAttributeMaxDynamicSharedMemorySize, SMEMB);
    cudaFuncSetAttribute(mma_gemm<1,2>, cudaFuncAttributeMaxDynamicSharedMemorySize, SMEMB);
    cudaFuncSetAttribute(mma_gemm<0,3>, cudaFuncAttributeMaxDynamicSharedMemorySize, SMEMB);

    // 1-2: gathers (te unscaled; ie carries the 32 factor)
    gather_split<<<NB * TT, 256>>>(targets, target_emb, te_h, te_l, NB * TT, 1.0f);
    gather_split<<<NB * TI, 256>>>(inputs, input_emb, ie_h, ie_l, NB * TI, 32.0f);

    // 3: fused ie hi+lo transpose (needs only ie)
    transpose_b2<<<dim3(HH/32, TI/32, 2*NB), dim3(32, 8)>>>(
        ie_h, ieT_h, ie_l, ieT_l, TI, HH, NB);

    // 4: logits = te @ (ie*32)^T   [B, TT, TI]   <-- PROFILED LAUNCH
    mma_gemm<0,0><<<dim3(TI/128, TT/128, NB), 256, SMEMB>>>(
        te_h, te_l, ie_h, ie_l, nullptr, lg, nullptr, nullptr,
        HH, HH, HH, TI, (size_t)TT*HH, (size_t)TI*HH, (size_t)TT*TI);

    // 5-6: weight transposes (needed only by G3/G4)
    transpose_split_w<<<dim3(UU/32, (3*HH)/32), dim3(32, 8)>>>(conv_w, cw_h, cw_l, 3*HH, UU);
    transpose_split_w<<<dim3(HH/32, UU/32), dim3(32, 8)>>>(dense_w, dw_h, dw_l, UU, HH);

    // 7: softmax -> prob splits
    softmax_split<<<NB * TT, 256>>>(lg, p_h, p_l);

    // 8: attn = P @ ie   [B, TT, HH]
    mma_gemm<0,1><<<dim3(HH/128, TT/128, NB), 256, SMEMB>>>(
        p_h, p_l, ieT_h, ieT_l, nullptr, nullptr, at_h, at_l,
        TI, TI, TI, HH, (size_t)TT*TI, (size_t)HH*TI, (size_t)TT*HH);

    // 9: h = relu(conv1d(attn) + conv_b)   [8192, UU] via implicit im2col
    mma_gemm<1,2><<<dim3(UU/128, (NB*TT)/128, 1), 256, SMEMB>>>(
        at_h, at_l, cw_h, cw_l, conv_b, nullptr, hb_h, hb_l,
        3*HH, 0, 3*HH, UU, 0, 0, 0);

    // 10: out = h @ dense_w + dense_b   [8192, HH]
    mma_gemm<0,3><<<dim3(HH/128, (NB*TT)/128, 1), 256, SMEMB>>>(
        hb_h, hb_l, dw_h, dw_l, dense_b, out, nullptr, nullptr,
        UU, UU, UU, HH, 0, 0, 0);
}

// round 11
// speedup vs baseline: 1.0812x; 1.0812x over previous
#include <cuda_runtime.h>
#include <cuda_bf16.h>
#include <stdint.h>
#include <math.h>

#define NB 4
#define TT 2048
#define TI 2048
#define HH 1024
#define UU 4096

typedef __nv_bfloat16 bf16;

// ---------------------------------------------------------------------------
// Scratch (allocation-free: __device__ globals)
// ---------------------------------------------------------------------------
__device__ bf16 g_te_h[(size_t)NB*TT*HH];
__device__ bf16 g_te_l[(size_t)NB*TT*HH];
__device__ bf16 g_ie_h[(size_t)NB*TI*HH];
__device__ bf16 g_ie_l[(size_t)NB*TI*HH];
__device__ bf16 g_ieT_h[(size_t)NB*HH*TI];
__device__ bf16 g_ieT_l[(size_t)NB*HH*TI];
__device__ float g_logits[(size_t)NB*TT*TI];
__device__ bf16 g_p_h[(size_t)NB*TT*TI];
__device__ bf16 g_p_l[(size_t)NB*TT*TI];
__device__ bf16 g_at_h[(size_t)NB*TT*HH];
__device__ bf16 g_at_l[(size_t)NB*TT*HH];
__device__ bf16 g_hb_h[(size_t)NB*TT*UU];
__device__ bf16 g_hb_l[(size_t)NB*TT*UU];
__device__ bf16 g_cw_h[(size_t)UU*3*HH];
__device__ bf16 g_cw_l[(size_t)UU*3*HH];
__device__ bf16 g_dw_h[(size_t)HH*UU];
__device__ bf16 g_dw_l[(size_t)HH*UU];

// ---------------------------------------------------------------------------
// Helpers
// ---------------------------------------------------------------------------
__device__ __forceinline__ uint32_t cvta_smem(const void* p) {
    uint32_t a;
    asm("{ .reg .u64 t; cvta.to.shared.u64 t, %1; cvt.u32.u64 %0, t; }"
        : "=r"(a) : "l"(p));
    return a;
}
__device__ __forceinline__ void bsplit(float v, bf16& h, bf16& l) {
    h = __float2bfloat16(v);
    l = __float2bfloat16(v - __bfloat162float(h));
}
__device__ __forceinline__ void cpa16(uint32_t d, const void* s) {
    asm volatile("cp.async.cg.shared.global [%0], [%1], 16;" :: "r"(d), "l"(s));
}
__device__ __forceinline__ void cpa16z(uint32_t d, const void* s, unsigned sz) {
    asm volatile("cp.async.cg.shared.global [%0], [%1], 16, %2;"
                 :: "r"(d), "l"(s), "r"(sz));
}
__device__ __forceinline__ void cpa_commit() {
    asm volatile("cp.async.commit_group;" ::: "memory");
}
template <int N>
__device__ __forceinline__ void cpa_wait() {
    asm volatile("cp.async.wait_group %0;" :: "n"(N) : "memory");
}
// SW64 swizzle: bits[4:5] ^= bits[7:8] (row stride 64B, conflict-free ldmatrix)
__device__ __forceinline__ uint32_t sw64(uint32_t o) {
    return o ^ ((o >> 3) & 0x30);
}

#define LDM4(f, a) \
    asm volatile("ldmatrix.sync.aligned.m8n8.x4.shared.b16 {%0,%1,%2,%3}, [%4];" \
        : "=r"((f)[0]), "=r"((f)[1]), "=r"((f)[2]), "=r"((f)[3]) : "r"(a))
#define MMA16816(d, a, b) \
    asm volatile("mma.sync.aligned.m16n8k16.row.col.f32.bf16.bf16.f32 " \
        "{%0,%1,%2,%3}, {%4,%5,%6,%7}, {%8,%9}, {%0,%1,%2,%3};" \
        : "+f"((d)[0]), "+f"((d)[1]), "+f"((d)[2]), "+f"((d)[3]) \
        : "r"((a)[0]), "r"((a)[1]), "r"((a)[2]), "r"((a)[3]), \
          "r"((b)[0]), "r"((b)[1]))

// ---------------------------------------------------------------------------
// Embedding gather + scale + bf16 hi/lo split
// ---------------------------------------------------------------------------
__global__ void gather_split(const int* __restrict__ idx, const float* __restrict__ emb,
                             bf16* __restrict__ oh, bf16* __restrict__ ol,
                             int n_tok, float scale) {
    int i = blockIdx.x * 256 + threadIdx.x;
    if (i >= n_tok * 256) return;
    int tok = i >> 8, h4 = i & 255;
    float4 v = ((const float4*)emb)[(size_t)idx[tok] * 256 + h4];
    float f[4] = {v.x * scale, v.y * scale, v.z * scale, v.w * scale};
    bf16 h[4], l[4];
    #pragma unroll
    for (int k = 0; k < 4; ++k) bsplit(f[k], h[k], l[k]);
    size_t o = (size_t)tok * HH + h4 * 4;
    __nv_bfloat162 a, b;
    a.x = h[0]; a.y = h[1]; b.x = h[2]; b.y = h[3];
    *(__nv_bfloat162*)(oh + o) = a; *(__nv_bfloat162*)(oh + o + 2) = b;
    a.x = l[0]; a.y = l[1]; b.x = l[2]; b.y = l[3];
    *(__nv_bfloat162*)(ol + o) = a; *(__nv_bfloat162*)(ol + o + 2) = b;
}

// ---------------------------------------------------------------------------
// bf16 transpose [R,C] -> [C,R]; z selects (batch, hi/lo plane)
// ---------------------------------------------------------------------------
__global__ void transpose_b2(const bf16* __restrict__ in0, bf16* __restrict__ out0,
                             const bf16* __restrict__ in1, bf16* __restrict__ out1,
                             int R, int C, int zsplit) {
    __shared__ bf16 t[32][33];
    int zz = blockIdx.z;
    const bf16* in;
    bf16* out;
    if (zz < zsplit) { in = in0 + (size_t)zz * R * C; out = out0 + (size_t)zz * R * C; }
    else { zz -= zsplit; in = in1 + (size_t)zz * R * C; out = out1 + (size_t)zz * R * C; }
    int c0 = blockIdx.x * 32, r0 = blockIdx.y * 32;
    for (int i = threadIdx.y; i < 32; i += 8)
        t[i][threadIdx.x] = in[(size_t)(r0 + i) * C + c0 + threadIdx.x];
    __syncthreads();
    for (int i = threadIdx.y; i < 32; i += 8)
        out[(size_t)(c0 + i) * R + r0 + threadIdx.x] = t[threadIdx.x][i];
}

// fp32 weight transpose [R,C] -> bf16 hi/lo [C,R]
__global__ void transpose_split_w(const float* __restrict__ in,
                                  bf16* __restrict__ oh, bf16* __restrict__ ol,
                                  int R, int C) {
    __shared__ float t[32][33];
    int c0 = blockIdx.x * 32, r0 = blockIdx.y * 32;
    for (int i = threadIdx.y; i < 32; i += 8)
        t[i][threadIdx.x] = in[(size_t)(r0 + i) * C + c0 + threadIdx.x];
    __syncthreads();
    for (int i = threadIdx.y; i < 32; i += 8) {
        bf16 h, l;
        bsplit(t[threadIdx.x][i], h, l);
        size_t o = (size_t)(c0 + i) * R + r0 + threadIdx.x;
        oh[o] = h; ol[o] = l;
    }
}

// ---------------------------------------------------------------------------
// Softmax over TI cols, writes bf16 hi/lo probabilities
// ---------------------------------------------------------------------------
__global__ void softmax_split(const float* __restrict__ logits,
                              bf16* __restrict__ ph_, bf16* __restrict__ pl_) {
    __shared__ float red[256];
    const int tid = threadIdx.x;
    const float4* p = (const float4*)(logits + (size_t)blockIdx.x * TI);
    float4 v0 = p[tid];
    float4 v1 = p[tid + 256];

    float m = fmaxf(fmaxf(fmaxf(v0.x, v0.y), fmaxf(v0.z, v0.w)),
                    fmaxf(fmaxf(v1.x, v1.y), fmaxf(v1.z, v1.w)));
    red[tid] = m;
    __syncthreads();
    #pragma unroll
    for (int s = 128; s > 0; s >>= 1) {
        if (tid < s) red[tid] = fmaxf(red[tid], red[tid + s]);
        __syncthreads();
    }
    m = red[0];
    __syncthreads();

    v0.x = expf(v0.x - m); v0.y = expf(v0.y - m);
    v0.z = expf(v0.z - m); v0.w = expf(v0.w - m);
    v1.x = expf(v1.x - m); v1.y = expf(v1.y - m);
    v1.z = expf(v1.z - m); v1.w = expf(v1.w - m);

    red[tid] = v0.x + v0.y + v0.z + v0.w + v1.x + v1.y + v1.z + v1.w;
    __syncthreads();
    #pragma unroll
    for (int s = 128; s > 0; s >>= 1) {
        if (tid < s) red[tid] += red[tid + s];
        __syncthreads();
    }
    float inv = 1.f / red[0];

    size_t base = (size_t)blockIdx.x * TI;
    float f[8] = {v0.x*inv, v0.y*inv, v0.z*inv, v0.w*inv,
                  v1.x*inv, v1.y*inv, v1.z*inv, v1.w*inv};
    #pragma unroll
    for (int g = 0; g < 2; ++g) {
        size_t o = base + (size_t)(tid + g * 256) * 4;
        bf16 h[4], l[4];
        #pragma unroll
        for (int k = 0; k < 4; ++k) bsplit(f[g*4 + k], h[k], l[k]);
        __nv_bfloat162 a, b;
        a.x = h[0]; a.y = h[1]; b.x = h[2]; b.y = h[3];
        *(__nv_bfloat162*)(ph_ + o) = a; *(__nv_bfloat162*)(ph_ + o + 2) = b;
        a.x = l[0]; a.y = l[1]; b.x = l[2]; b.y = l[3];
        *(__nv_bfloat162*)(pl_ + o) = a; *(__nv_bfloat162*)(pl_ + o + 2) = b;
    }
}

// ---------------------------------------------------------------------------
// bf16x3 GEMM via mma.sync: 128x128 CTA tile, FOUR warps (64x64 warp tile),
// BK=32, SW64-swizzled smem, 3-stage cp.async pipeline (R9 sync pattern),
// 2 CTAs/SM. Bigger warp tile halves A-fragment LDSM redundancy (4x -> 2x).
// ---------------------------------------------------------------------------
#define TILE_T 8192             // 128 rows * 64B (SW64 swizzled, no pad)
#define STAGE_B (4 * TILE_T)    // Ah, Al, Bh, Bl = 32768
#define NSTAGE 3

template <int AMODE, int EPI>
__global__ __launch_bounds__(128, 2)
void mma_gemm(const bf16* __restrict__ Ah_, const bf16* __restrict__ Al_,
              const bf16* __restrict__ Bh_, const bf16* __restrict__ Bl_,
              const float* __restrict__ bias,
              float* __restrict__ Cf, bf16* __restrict__ Ch, bf16* __restrict__ Cl,
              int K, int lda, int ldb, int ldc,
              size_t sA, size_t sB, size_t sC)
{
    extern __shared__ char smem[];
    const uint32_t sbase = cvta_smem(smem);
    const int tid  = threadIdx.x;
    const int lane = tid & 31;
    const int wid  = tid >> 5;      // 0..3
    const int wm   = wid & 1;       // 64-row slab
    const int wn   = wid >> 1;      // 64-col slab

    const size_t z = blockIdx.z;
    Ah_ += z * sA; Al_ += z * sA;
    Bh_ += z * sB; Bl_ += z * sB;
    if (Cf) Cf += z * sC;
    if (Ch) { Ch += z * sC; Cl += z * sC; }

    const int bm = blockIdx.y * 128;
    const int bn = blockIdx.x * 128;
    const int KT = K >> 5;

    float acc[4][8][4];
    #pragma unroll
    for (int a = 0; a < 4; ++a)
        #pragma unroll
        for (int b = 0; b < 8; ++b)
            #pragma unroll
            for (int c = 0; c < 4; ++c) acc[a][b][c] = 0.f;

    // ---- stage loader: 4 tiles x 512 16B-chunks, 128 threads -> 16/thread
    auto load_stage = [&](int slot, int kt) {
        const int k0 = kt * 32;
        const uint32_t sb = sbase + slot * STAGE_B;
        #pragma unroll
        for (int half = 0; half < 4; ++half) {
            const int idx = tid + half * 128;   // 0..511
            const int r = idx >> 2;
            const int c = idx & 3;
            const uint32_t so = sw64((uint32_t)(r * 64 + c * 16));
            // A hi/lo
            if (AMODE == 0) {
                cpa16(sb + so,          Ah_ + (size_t)(bm + r) * lda + k0 + c * 8);
                cpa16(sb + TILE_T + so, Al_ + (size_t)(bm + r) * lda + k0 + c * 8);
            } else {
                const int tap = k0 >> 10;
                const int ccol = (k0 & 1023) + c * 8;
                const int m = bm + r;
                const int b = m >> 11;
                const int t = (m & 2047) + tap - 1;
                const unsigned ok = ((unsigned)t < 2048u) ? 16u : 0u;
                const size_t o = ((size_t)b * 2048 + (ok ? t : 0)) * 1024 + ccol;
                cpa16z(sb + so,          Ah_ + o, ok);
                cpa16z(sb + TILE_T + so, Al_ + o, ok);
            }
            // B hi/lo
            cpa16(sb + 2 * TILE_T + so, Bh_ + (size_t)(bn + r) * ldb + k0 + c * 8);
            cpa16(sb + 3 * TILE_T + so, Bl_ + (size_t)(bn + r) * ldb + k0 + c * 8);
        }
        cpa_commit();
    };

    load_stage(0, 0);
    load_stage(1, 1);

    for (int kt = 0; kt < KT; ++kt) {
        if (kt + 1 < KT) cpa_wait<1>(); else cpa_wait<0>();  // stage kt landed
        __syncthreads();   // all warps past iteration kt-1 reads; see stage kt
        if (kt + 2 < KT) load_stage((kt + 2) % NSTAGE, kt + 2);

        const uint32_t sb  = sbase + (kt % NSTAGE) * STAGE_B;
        const uint32_t sbB = sb + 2 * TILE_T;
        #pragma unroll
        for (int ks = 0; ks < 2; ++ks) {
            uint32_t Ahf[4][4], Alf[4][4];
            const int arow  = wm * 64 + (lane & 15);
            const int ahalf = lane >> 4;
            #pragma unroll
            for (int mf = 0; mf < 4; ++mf) {
                const uint32_t ao = sw64((uint32_t)((arow + mf * 16) * 64
                                  + (ks * 2 + ahalf) * 16));
                LDM4(Ahf[mf], sb + ao);
                LDM4(Alf[mf], sb + TILE_T + ao);
            }
            // B: paired x4 loads (2 nf-cols per LDM4); np 0..3 covers 64 cols
            const int bmat = lane >> 3;           // 0..3
            const int brow0 = wn * 64 + (lane & 7) + (bmat >> 1) * 8;
            const int bko = (ks * 2 + (bmat & 1)) * 16;
            #pragma unroll
            for (int np = 0; np < 4; ++np) {
                uint32_t Bhf[4], Blf[4];
                const uint32_t bo = sw64((uint32_t)((brow0 + np * 16) * 64 + bko));
                LDM4(Bhf, sbB + bo);
                LDM4(Blf, sbB + TILE_T + bo);
                // term-major across both n-subtiles: same-acc reuse = 8 MMAs
                #pragma unroll
                for (int sub = 0; sub < 2; ++sub)
                    #pragma unroll
                    for (int mf = 0; mf < 4; ++mf)
                        MMA16816(acc[mf][np * 2 + sub], Ahf[mf], &Bhf[sub * 2]);
                #pragma unroll
                for (int sub = 0; sub < 2; ++sub)
                    #pragma unroll
                    for (int mf = 0; mf < 4; ++mf)
                        MMA16816(acc[mf][np * 2 + sub], Ahf[mf], &Blf[sub * 2]);
                #pragma unroll
                for (int sub = 0; sub < 2; ++sub)
                    #pragma unroll
                    for (int mf = 0; mf < 4; ++mf)
                        MMA16816(acc[mf][np * 2 + sub], Alf[mf], &Bhf[sub * 2]);
            }
        }
    }

    // ---- epilogue
    const int mrow = bm + wm * 64 + (lane >> 2);
    const int ncol = bn + wn * 64 + (lane & 3) * 2;
    #pragma unroll
    for (int mf = 0; mf < 4; ++mf) {
        #pragma unroll
        for (int nf = 0; nf < 8; ++nf) {
            const float* a4 = acc[mf][nf];
            #pragma unroll
            for (int h = 0; h < 2; ++h) {
                const int m = mrow + mf * 16 + h * 8;
                const int n = ncol + nf * 8;
                float v0 = a4[h * 2 + 0];
                float v1 = a4[h * 2 + 1];
                if (EPI == 0) {
                    *(float2*)(Cf + (size_t)m * ldc + n) = make_float2(v0, v1);
                } else if (EPI == 3) {
                    *(float2*)(Cf + (size_t)m * ldc + n) =
                        make_float2(v0 + bias[n], v1 + bias[n + 1]);
                } else {
                    if (EPI == 2) {
                        v0 = fmaxf(v0 + bias[n], 0.f);
                        v1 = fmaxf(v1 + bias[n + 1], 0.f);
                    }
                    bf16 h0, l0, h1, l1;
                    bsplit(v0, h0, l0);
                    bsplit(v1, h1, l1);
                    __nv_bfloat162 vh, vl;
                    vh.x = h0; vh.y = h1;
                    vl.x = l0; vl.y = l1;
                    *(__nv_bfloat162*)(Ch + (size_t)m * ldc + n) = vh;
                    *(__nv_bfloat162*)(Cl + (size_t)m * ldc + n) = vl;
                }
            }
        }
    }
}

// ---------------------------------------------------------------------------
extern "C" void kernel_launch(void* const* d_in, const int* in_sizes, int n_in,
                              void* d_out, int out_size) {
    const int*   inputs     = (const int*)d_in[0];
    const int*   targets    = (const int*)d_in[1];
    const float* input_emb  = (const float*)d_in[2];
    const float* target_emb = (const float*)d_in[3];
    const float* conv_w     = (const float*)d_in[4];
    const float* conv_b     = (const float*)d_in[5];
    const float* dense_w    = (const float*)d_in[6];
    const float* dense_b    = (const float*)d_in[7];
    float* out = (float*)d_out;

    bf16 *te_h, *te_l, *ie_h, *ie_l, *ieT_h, *ieT_l, *p_h, *p_l;
    bf16 *at_h, *at_l, *hb_h, *hb_l, *cw_h, *cw_l, *dw_h, *dw_l;
    float* lg;
    cudaGetSymbolAddress((void**)&te_h, g_te_h);
    cudaGetSymbolAddress((void**)&te_l, g_te_l);
    cudaGetSymbolAddress((void**)&ie_h, g_ie_h);
    cudaGetSymbolAddress((void**)&ie_l, g_ie_l);
    cudaGetSymbolAddress((void**)&ieT_h, g_ieT_h);
    cudaGetSymbolAddress((void**)&ieT_l, g_ieT_l);
    cudaGetSymbolAddress((void**)&lg, g_logits);
    cudaGetSymbolAddress((void**)&p_h, g_p_h);
    cudaGetSymbolAddress((void**)&p_l, g_p_l);
    cudaGetSymbolAddress((void**)&at_h, g_at_h);
    cudaGetSymbolAddress((void**)&at_l, g_at_l);
    cudaGetSymbolAddress((void**)&hb_h, g_hb_h);
    cudaGetSymbolAddress((void**)&hb_l, g_hb_l);
    cudaGetSymbolAddress((void**)&cw_h, g_cw_h);
    cudaGetSymbolAddress((void**)&cw_l, g_cw_l);
    cudaGetSymbolAddress((void**)&dw_h, g_dw_h);
    cudaGetSymbolAddress((void**)&dw_l, g_dw_l);

    const int SMEMB = NSTAGE * STAGE_B;  // 98304 -> 2 CTAs/SM
    cudaFuncSetAttribute(mma_gemm<0,0>, cudaFuncAttributeMaxDynamicSharedMemorySize, SMEMB);
    cudaFuncSetAttribute(mma_gemm<0,1>, cudaFuncAttributeMaxDynamicSharedMemorySize, SMEMB);
    cudaFuncSetAttribute(mma_gemm<1,2>, cudaFuncAttributeMaxDynamicSharedMemorySize, SMEMB);
    cudaFuncSetAttribute(mma_gemm<0,3>, cudaFuncAttributeMaxDynamicSharedMemorySize, SMEMB);

    // 1-2: gathers (te unscaled; ie carries the 32 factor)
    gather_split<<<NB * TT, 256>>>(targets, target_emb, te_h, te_l, NB * TT, 1.0f);
    gather_split<<<NB * TI, 256>>>(inputs, input_emb, ie_h, ie_l, NB * TI, 32.0f);

    // 3: fused ie hi+lo transpose (needs only ie)
    transpose_b2<<<dim3(HH/32, TI/32, 2*NB), dim3(32, 8)>>>(
        ie_h, ieT_h, ie_l, ieT_l, TI, HH, NB);

    // 4: logits = te @ (ie*32)^T   [B, TT, TI]   <-- PROFILED LAUNCH
    mma_gemm<0,0><<<dim3(TI/128, TT/128, NB), 128, SMEMB>>>(
        te_h, te_l, ie_h, ie_l, nullptr, lg, nullptr, nullptr,
        HH, HH, HH, TI, (size_t)TT*HH, (size_t)TI*HH, (size_t)TT*TI);

    // 5-6: weight transposes (needed only by G3/G4)
    transpose_split_w<<<dim3(UU/32, (3*HH)/32), dim3(32, 8)>>>(conv_w, cw_h, cw_l, 3*HH, UU);
    transpose_split_w<<<dim3(HH/32, UU/32), dim3(32, 8)>>>(dense_w, dw_h, dw_l, UU, HH);

    // 7: softmax -> prob splits
    softmax_split<<<NB * TT, 256>>>(lg, p_h, p_l);

    // 8: attn = P @ ie   [B, TT, HH]
    mma_gemm<0,1><<<dim3(HH/128, TT/128, NB), 128, SMEMB>>>(
        p_h, p_l, ieT_h, ieT_l, nullptr, nullptr, at_h, at_l,
        TI, TI, TI, HH, (size_t)TT*TI, (size_t)HH*TI, (size_t)TT*HH);

    // 9: h = relu(conv1d(attn) + conv_b)   [8192, UU] via implicit im2col
    mma_gemm<1,2><<<dim3(UU/128, (NB*TT)/128, 1), 128, SMEMB>>>(
        at_h, at_l, cw_h, cw_l, conv_b, nullptr, hb_h, hb_l,
        3*HH, 0, 3*HH, UU, 0, 0, 0);

    // 10: out = h @ dense_w + dense_b   [8192, HH]
    mma_gemm<0,3><<<dim3(HH/128, (NB*TT)/128, 1), 128, SMEMB>>>(
        hb_h, hb_l, dw_h, dw_l, dense_b, out, nullptr, nullptr,
        UU, UU, UU, HH, 0, 0, 0);
}

// round 12
// speedup vs baseline: 1.2116x; 1.1206x over previous
#include <cuda_runtime.h>
#include <cuda_bf16.h>
#include <stdint.h>
#include <math.h>

#define NB 4
#define TT 2048
#define TI 2048
#define HH 1024
#define UU 4096

typedef __nv_bfloat16 bf16;

// ---------------------------------------------------------------------------
// Scratch (allocation-free: __device__ globals)
// ---------------------------------------------------------------------------
__device__ bf16 g_te_h[(size_t)NB*TT*HH];
__device__ bf16 g_te_l[(size_t)NB*TT*HH];
__device__ bf16 g_ie_h[(size_t)NB*TI*HH];
__device__ bf16 g_ie_l[(size_t)NB*TI*HH];
__device__ bf16 g_ieT_h[(size_t)NB*HH*TI];
__device__ bf16 g_ieT_l[(size_t)NB*HH*TI];
__device__ float g_logits[(size_t)NB*TT*TI];
__device__ bf16 g_p_h[(size_t)NB*TT*TI];
__device__ bf16 g_p_l[(size_t)NB*TT*TI];
__device__ bf16 g_at_h[(size_t)NB*TT*HH];
__device__ bf16 g_at_l[(size_t)NB*TT*HH];
__device__ bf16 g_hb_h[(size_t)NB*TT*UU];
__device__ bf16 g_hb_l[(size_t)NB*TT*UU];
__device__ bf16 g_cw_h[(size_t)UU*3*HH];
__device__ bf16 g_cw_l[(size_t)UU*3*HH];
__device__ bf16 g_dw_h[(size_t)HH*UU];
__device__ bf16 g_dw_l[(size_t)HH*UU];

// ---------------------------------------------------------------------------
// Helpers
// ---------------------------------------------------------------------------
__device__ __forceinline__ uint32_t cvta_smem(const void* p) {
    uint32_t a;
    asm("{ .reg .u64 t; cvta.to.shared.u64 t, %1; cvt.u32.u64 %0, t; }"
        : "=r"(a) : "l"(p));
    return a;
}
__device__ __forceinline__ void bsplit(float v, bf16& h, bf16& l) {
    h = __float2bfloat16(v);
    l = __float2bfloat16(v - __bfloat162float(h));
}
__device__ __forceinline__ void cpa16(uint32_t d, const void* s) {
    asm volatile("cp.async.cg.shared.global [%0], [%1], 16;" :: "r"(d), "l"(s));
}
__device__ __forceinline__ void cpa16z(uint32_t d, const void* s, unsigned sz) {
    asm volatile("cp.async.cg.shared.global [%0], [%1], 16, %2;"
                 :: "r"(d), "l"(s), "r"(sz));
}
__device__ __forceinline__ void cpa_commit() {
    asm volatile("cp.async.commit_group;" ::: "memory");
}
template <int N>
__device__ __forceinline__ void cpa_wait() {
    asm volatile("cp.async.wait_group %0;" :: "n"(N) : "memory");
}
// SW64 swizzle: bits[4:5] ^= bits[7:8] (row stride 64B, conflict-free ldmatrix)
__device__ __forceinline__ uint32_t sw64(uint32_t o) {
    return o ^ ((o >> 3) & 0x30);
}

#define LDM4(f, a) \
    asm volatile("ldmatrix.sync.aligned.m8n8.x4.shared.b16 {%0,%1,%2,%3}, [%4];" \
        : "=r"((f)[0]), "=r"((f)[1]), "=r"((f)[2]), "=r"((f)[3]) : "r"(a))
#define MMA16816(d, a, b) \
    asm volatile("mma.sync.aligned.m16n8k16.row.col.f32.bf16.bf16.f32 " \
        "{%0,%1,%2,%3}, {%4,%5,%6,%7}, {%8,%9}, {%0,%1,%2,%3};" \
        : "+f"((d)[0]), "+f"((d)[1]), "+f"((d)[2]), "+f"((d)[3]) \
        : "r"((a)[0]), "r"((a)[1]), "r"((a)[2]), "r"((a)[3]), \
          "r"((b)[0]), "r"((b)[1]))

// ---------------------------------------------------------------------------
// Embedding gather + scale + bf16 hi/lo split
// ---------------------------------------------------------------------------
__global__ void gather_split(const int* __restrict__ idx, const float* __restrict__ emb,
                             bf16* __restrict__ oh, bf16* __restrict__ ol,
                             int n_tok, float scale) {
    int i = blockIdx.x * 256 + threadIdx.x;
    if (i >= n_tok * 256) return;
    int tok = i >> 8, h4 = i & 255;
    float4 v = ((const float4*)emb)[(size_t)idx[tok] * 256 + h4];
    float f[4] = {v.x * scale, v.y * scale, v.z * scale, v.w * scale};
    bf16 h[4], l[4];
    #pragma unroll
    for (int k = 0; k < 4; ++k) bsplit(f[k], h[k], l[k]);
    size_t o = (size_t)tok * HH + h4 * 4;
    __nv_bfloat162 a, b;
    a.x = h[0]; a.y = h[1]; b.x = h[2]; b.y = h[3];
    *(__nv_bfloat162*)(oh + o) = a; *(__nv_bfloat162*)(oh + o + 2) = b;
    a.x = l[0]; a.y = l[1]; b.x = l[2]; b.y = l[3];
    *(__nv_bfloat162*)(ol + o) = a; *(__nv_bfloat162*)(ol + o + 2) = b;
}

// ---------------------------------------------------------------------------
// bf16 transpose [R,C] -> [C,R]; z selects (batch, hi/lo plane)
// ---------------------------------------------------------------------------
__global__ void transpose_b2(const bf16* __restrict__ in0, bf16* __restrict__ out0,
                             const bf16* __restrict__ in1, bf16* __restrict__ out1,
                             int R, int C, int zsplit) {
    __shared__ bf16 t[32][33];
    int zz = blockIdx.z;
    const bf16* in;
    bf16* out;
    if (zz < zsplit) { in = in0 + (size_t)zz * R * C; out = out0 + (size_t)zz * R * C; }
    else { zz -= zsplit; in = in1 + (size_t)zz * R * C; out = out1 + (size_t)zz * R * C; }
    int c0 = blockIdx.x * 32, r0 = blockIdx.y * 32;
    for (int i = threadIdx.y; i < 32; i += 8)
        t[i][threadIdx.x] = in[(size_t)(r0 + i) * C + c0 + threadIdx.x];
    __syncthreads();
    for (int i = threadIdx.y; i < 32; i += 8)
        out[(size_t)(c0 + i) * R + r0 + threadIdx.x] = t[threadIdx.x][i];
}

// fp32 weight transpose [R,C] -> bf16 hi/lo [C,R]
__global__ void transpose_split_w(const float* __restrict__ in,
                                  bf16* __restrict__ oh, bf16* __restrict__ ol,
                                  int R, int C) {
    __shared__ float t[32][33];
    int c0 = blockIdx.x * 32, r0 = blockIdx.y * 32;
    for (int i = threadIdx.y; i < 32; i += 8)
        t[i][threadIdx.x] = in[(size_t)(r0 + i) * C + c0 + threadIdx.x];
    __syncthreads();
    for (int i = threadIdx.y; i < 32; i += 8) {
        bf16 h, l;
        bsplit(t[threadIdx.x][i], h, l);
        size_t o = (size_t)(c0 + i) * R + r0 + threadIdx.x;
        oh[o] = h; ol[o] = l;
    }
}

// ---------------------------------------------------------------------------
// Softmax over TI cols, writes bf16 hi/lo probabilities
// ---------------------------------------------------------------------------
__global__ void softmax_split(const float* __restrict__ logits,
                              bf16* __restrict__ ph_, bf16* __restrict__ pl_) {
    __shared__ float red[256];
    const int tid = threadIdx.x;
    const float4* p = (const float4*)(logits + (size_t)blockIdx.x * TI);
    float4 v0 = p[tid];
    float4 v1 = p[tid + 256];

    float m = fmaxf(fmaxf(fmaxf(v0.x, v0.y), fmaxf(v0.z, v0.w)),
                    fmaxf(fmaxf(v1.x, v1.y), fmaxf(v1.z, v1.w)));
    red[tid] = m;
    __syncthreads();
    #pragma unroll
    for (int s = 128; s > 0; s >>= 1) {
        if (tid < s) red[tid] = fmaxf(red[tid], red[tid + s]);
        __syncthreads();
    }
    m = red[0];
    __syncthreads();

    v0.x = expf(v0.x - m); v0.y = expf(v0.y - m);
    v0.z = expf(v0.z - m); v0.w = expf(v0.w - m);
    v1.x = expf(v1.x - m); v1.y = expf(v1.y - m);
    v1.z = expf(v1.z - m); v1.w = expf(v1.w - m);

    red[tid] = v0.x + v0.y + v0.z + v0.w + v1.x + v1.y + v1.z + v1.w;
    __syncthreads();
    #pragma unroll
    for (int s = 128; s > 0; s >>= 1) {
        if (tid < s) red[tid] += red[tid + s];
        __syncthreads();
    }
    float inv = 1.f / red[0];

    size_t base = (size_t)blockIdx.x * TI;
    float f[8] = {v0.x*inv, v0.y*inv, v0.z*inv, v0.w*inv,
                  v1.x*inv, v1.y*inv, v1.z*inv, v1.w*inv};
    #pragma unroll
    for (int g = 0; g < 2; ++g) {
        size_t o = base + (size_t)(tid + g * 256) * 4;
        bf16 h[4], l[4];
        #pragma unroll
        for (int k = 0; k < 4; ++k) bsplit(f[g*4 + k], h[k], l[k]);
        __nv_bfloat162 a, b;
        a.x = h[0]; a.y = h[1]; b.x = h[2]; b.y = h[3];
        *(__nv_bfloat162*)(ph_ + o) = a; *(__nv_bfloat162*)(ph_ + o + 2) = b;
        a.x = l[0]; a.y = l[1]; b.x = l[2]; b.y = l[3];
        *(__nv_bfloat162*)(pl_ + o) = a; *(__nv_bfloat162*)(pl_ + o + 2) = b;
    }
}

// ---------------------------------------------------------------------------
// bf16x3 GEMM via mma.sync: 128x128 CTA tile, FOUR warps (64x64 warp tile),
// BK=32, SW64-swizzled smem, 3-stage cp.async pipeline, 2 CTAs/SM.
// R12: cp.async issuance moved BETWEEN ks=0 and ks=1 (off the critical head);
// wait discipline identical to R11 (cpa_wait<1> at top of kt).
// ---------------------------------------------------------------------------
#define TILE_T 8192             // 128 rows * 64B (SW64 swizzled, no pad)
#define STAGE_B (4 * TILE_T)    // Ah, Al, Bh, Bl = 32768
#define NSTAGE 3

template <int AMODE, int EPI>
__global__ __launch_bounds__(128, 2)
void mma_gemm(const bf16* __restrict__ Ah_, const bf16* __restrict__ Al_,
              const bf16* __restrict__ Bh_, const bf16* __restrict__ Bl_,
              const float* __restrict__ bias,
              float* __restrict__ Cf, bf16* __restrict__ Ch, bf16* __restrict__ Cl,
              int K, int lda, int ldb, int ldc,
              size_t sA, size_t sB, size_t sC)
{
    extern __shared__ char smem[];
    const uint32_t sbase = cvta_smem(smem);
    const int tid  = threadIdx.x;
    const int lane = tid & 31;
    const int wid  = tid >> 5;      // 0..3
    const int wm   = wid & 1;       // 64-row slab
    const int wn   = wid >> 1;      // 64-col slab

    const size_t z = blockIdx.z;
    Ah_ += z * sA; Al_ += z * sA;
    Bh_ += z * sB; Bl_ += z * sB;
    if (Cf) Cf += z * sC;
    if (Ch) { Ch += z * sC; Cl += z * sC; }

    const int bm = blockIdx.y * 128;
    const int bn = blockIdx.x * 128;
    const int KT = K >> 5;

    float acc[4][8][4];
    #pragma unroll
    for (int a = 0; a < 4; ++a)
        #pragma unroll
        for (int b = 0; b < 8; ++b)
            #pragma unroll
            for (int c = 0; c < 4; ++c) acc[a][b][c] = 0.f;

    // ---- stage loader: 4 tiles x 512 16B-chunks, 128 threads -> 16/thread
    auto load_stage = [&](int slot, int kt) {
        const int k0 = kt * 32;
        const uint32_t sb = sbase + slot * STAGE_B;
        #pragma unroll
        for (int half = 0; half < 4; ++half) {
            const int idx = tid + half * 128;   // 0..511
            const int r = idx >> 2;
            const int c = idx & 3;
            const uint32_t so = sw64((uint32_t)(r * 64 + c * 16));
            // A hi/lo
            if (AMODE == 0) {
                cpa16(sb + so,          Ah_ + (size_t)(bm + r) * lda + k0 + c * 8);
                cpa16(sb + TILE_T + so, Al_ + (size_t)(bm + r) * lda + k0 + c * 8);
            } else {
                const int tap = k0 >> 10;
                const int ccol = (k0 & 1023) + c * 8;
                const int m = bm + r;
                const int b = m >> 11;
                const int t = (m & 2047) + tap - 1;
                const unsigned ok = ((unsigned)t < 2048u) ? 16u : 0u;
                const size_t o = ((size_t)b * 2048 + (ok ? t : 0)) * 1024 + ccol;
                cpa16z(sb + so,          Ah_ + o, ok);
                cpa16z(sb + TILE_T + so, Al_ + o, ok);
            }
            // B hi/lo
            cpa16(sb + 2 * TILE_T + so, Bh_ + (size_t)(bn + r) * ldb + k0 + c * 8);
            cpa16(sb + 3 * TILE_T + so, Bl_ + (size_t)(bn + r) * ldb + k0 + c * 8);
        }
        cpa_commit();
    };

    // ---- one ks half-step (16 K-values) from slot base sb
    auto compute_ks = [&](uint32_t sb, int ks) {
        const uint32_t sbB = sb + 2 * TILE_T;
        uint32_t Ahf[4][4], Alf[4][4];
        const int arow  = wm * 64 + (lane & 15);
        const int ahalf = lane >> 4;
        #pragma unroll
        for (int mf = 0; mf < 4; ++mf) {
            const uint32_t ao = sw64((uint32_t)((arow + mf * 16) * 64
                              + (ks * 2 + ahalf) * 16));
            LDM4(Ahf[mf], sb + ao);
            LDM4(Alf[mf], sb + TILE_T + ao);
        }
        const int bmat = lane >> 3;           // 0..3
        const int brow0 = wn * 64 + (lane & 7) + (bmat >> 1) * 8;
        const int bko = (ks * 2 + (bmat & 1)) * 16;
        #pragma unroll
        for (int np = 0; np < 4; ++np) {
            uint32_t Bhf[4], Blf[4];
            const uint32_t bo = sw64((uint32_t)((brow0 + np * 16) * 64 + bko));
            LDM4(Bhf, sbB + bo);
            LDM4(Blf, sbB + TILE_T + bo);
            // term-major across both n-subtiles: same-acc reuse = 8 MMAs
            #pragma unroll
            for (int sub = 0; sub < 2; ++sub)
                #pragma unroll
                for (int mf = 0; mf < 4; ++mf)
                    MMA16816(acc[mf][np * 2 + sub], Ahf[mf], &Bhf[sub * 2]);
            #pragma unroll
            for (int sub = 0; sub < 2; ++sub)
                #pragma unroll
                for (int mf = 0; mf < 4; ++mf)
                    MMA16816(acc[mf][np * 2 + sub], Ahf[mf], &Blf[sub * 2]);
            #pragma unroll
            for (int sub = 0; sub < 2; ++sub)
                #pragma unroll
                for (int mf = 0; mf < 4; ++mf)
                    MMA16816(acc[mf][np * 2 + sub], Alf[mf], &Bhf[sub * 2]);
        }
    };

    load_stage(0, 0);
    load_stage(1, 1);

    for (int kt = 0; kt < KT; ++kt) {
        if (kt + 1 < KT) cpa_wait<1>(); else cpa_wait<0>();  // stage kt landed
        __syncthreads();   // all warps past iteration kt-1 reads; see stage kt
        const uint32_t sb = sbase + (kt % NSTAGE) * STAGE_B;
        compute_ks(sb, 0);                                   // MMAs start now
        if (kt + 2 < KT) load_stage((kt + 2) % NSTAGE, kt + 2);  // in MMA shadow
        compute_ks(sb, 1);
    }

    // ---- epilogue
    const int mrow = bm + wm * 64 + (lane >> 2);
    const int ncol = bn + wn * 64 + (lane & 3) * 2;
    #pragma unroll
    for (int mf = 0; mf < 4; ++mf) {
        #pragma unroll
        for (int nf = 0; nf < 8; ++nf) {
            const float* a4 = acc[mf][nf];
            #pragma unroll
            for (int h = 0; h < 2; ++h) {
                const int m = mrow + mf * 16 + h * 8;
                const int n = ncol + nf * 8;
                float v0 = a4[h * 2 + 0];
                float v1 = a4[h * 2 + 1];
                if (EPI == 0) {
                    *(float2*)(Cf + (size_t)m * ldc + n) = make_float2(v0, v1);
                } else if (EPI == 3) {
                    *(float2*)(Cf + (size_t)m * ldc + n) =
                        make_float2(v0 + bias[n], v1 + bias[n + 1]);
                } else {
                    if (EPI == 2) {
                        v0 = fmaxf(v0 + bias[n], 0.f);
                        v1 = fmaxf(v1 + bias[n + 1], 0.f);
                    }
                    bf16 h0, l0, h1, l1;
                    bsplit(v0, h0, l0);
                    bsplit(v1, h1, l1);
                    __nv_bfloat162 vh, vl;
                    vh.x = h0; vh.y = h1;
                    vl.x = l0; vl.y = l1;
                    *(__nv_bfloat162*)(Ch + (size_t)m * ldc + n) = vh;
                    *(__nv_bfloat162*)(Cl + (size_t)m * ldc + n) = vl;
                }
            }
        }
    }
}

// ---------------------------------------------------------------------------
extern "C" void kernel_launch(void* const* d_in, const int* in_sizes, int n_in,
                              void* d_out, int out_size) {
    const int*   inputs     = (const int*)d_in[0];
    const int*   targets    = (const int*)d_in[1];
    const float* input_emb  = (const float*)d_in[2];
    const float* target_emb = (const float*)d_in[3];
    const float* conv_w     = (const float*)d_in[4];
    const float* conv_b     = (const float*)d_in[5];
    const float* dense_w    = (const float*)d_in[6];
    const float* dense_b    = (const float*)d_in[7];
    float* out = (float*)d_out;

    bf16 *te_h, *te_l, *ie_h, *ie_l, *ieT_h, *ieT_l, *p_h, *p_l;
    bf16 *at_h, *at_l, *hb_h, *hb_l, *cw_h, *cw_l, *dw_h, *dw_l;
    float* lg;
    cudaGetSymbolAddress((void**)&te_h, g_te_h);
    cudaGetSymbolAddress((void**)&te_l, g_te_l);
    cudaGetSymbolAddress((void**)&ie_h, g_ie_h);
    cudaGetSymbolAddress((void**)&ie_l, g_ie_l);
    cudaGetSymbolAddress((void**)&ieT_h, g_ieT_h);
    cudaGetSymbolAddress((void**)&ieT_l, g_ieT_l);
    cudaGetSymbolAddress((void**)&lg, g_logits);
    cudaGetSymbolAddress((void**)&p_h, g_p_h);
    cudaGetSymbolAddress((void**)&p_l, g_p_l);
    cudaGetSymbolAddress((void**)&at_h, g_at_h);
    cudaGetSymbolAddress((void**)&at_l, g_at_l);
    cudaGetSymbolAddress((void**)&hb_h, g_hb_h);
    cudaGetSymbolAddress((void**)&hb_l, g_hb_l);
    cudaGetSymbolAddress((void**)&cw_h, g_cw_h);
    cudaGetSymbolAddress((void**)&cw_l, g_cw_l);
    cudaGetSymbolAddress((void**)&dw_h, g_dw_h);
    cudaGetSymbolAddress((void**)&dw_l, g_dw_l);

    const int SMEMB = NSTAGE * STAGE_B;  // 98304 -> 2 CTAs/SM
    cudaFuncSetAttribute(mma_gemm<0,0>, cudaFuncAttributeMaxDynamicSharedMemorySize, SMEMB);
    cudaFuncSetAttribute(mma_gemm<0,1>, cudaFuncAttributeMaxDynamicSharedMemorySize, SMEMB);
    cudaFuncSetAttribute(mma_gemm<1,2>, cudaFuncAttributeMaxDynamicSharedMemorySize, SMEMB);
    cudaFuncSetAttribute(mma_gemm<0,3>, cudaFuncAttributeMaxDynamicSharedMemorySize, SMEMB);

    // 1-2: gathers (te unscaled; ie carries the 32 factor)
    gather_split<<<NB * TT, 256>>>(targets, target_emb, te_h, te_l, NB * TT, 1.0f);
    gather_split<<<NB * TI, 256>>>(inputs, input_emb, ie_h, ie_l, NB * TI, 32.0f);

    // 3: fused ie hi+lo transpose (needs only ie)
    transpose_b2<<<dim3(HH/32, TI/32, 2*NB), dim3(32, 8)>>>(
        ie_h, ieT_h, ie_l, ieT_l, TI, HH, NB);

    // 4: logits = te @ (ie*32)^T   [B, TT, TI]   <-- PROFILED LAUNCH
    mma_gemm<0,0><<<dim3(TI/128, TT/128, NB), 128, SMEMB>>>(
        te_h, te_l, ie_h, ie_l, nullptr, lg, nullptr, nullptr,
        HH, HH, HH, TI, (size_t)TT*HH, (size_t)TI*HH, (size_t)TT*TI);

    // 5-6: weight transposes (needed only by G3/G4)
    transpose_split_w<<<dim3(UU/32, (3*HH)/32), dim3(32, 8)>>>(conv_w, cw_h, cw_l, 3*HH, UU);
    transpose_split_w<<<dim3(HH/32, UU/32), dim3(32, 8)>>>(dense_w, dw_h, dw_l, UU, HH);

    // 7: softmax -> prob splits
    softmax_split<<<NB * TT, 256>>>(lg, p_h, p_l);

    // 8: attn = P @ ie   [B, TT, HH]
    mma_gemm<0,1><<<dim3(HH/128, TT/128, NB), 128, SMEMB>>>(
        p_h, p_l, ieT_h, ieT_l, nullptr, nullptr, at_h, at_l,
        TI, TI, TI, HH, (size_t)TT*TI, (size_t)HH*TI, (size_t)TT*HH);

    // 9: h = relu(conv1d(attn) + conv_b)   [8192, UU] via implicit im2col
    mma_gemm<1,2><<<dim3(UU/128, (NB*TT)/128, 1), 128, SMEMB>>>(
        at_h, at_l, cw_h, cw_l, conv_b, nullptr, hb_h, hb_l,
        3*HH, 0, 3*HH, UU, 0, 0, 0);

    // 10: out = h @ dense_w + dense_b   [8192, HH]
    mma_gemm<0,3><<<dim3(HH/128, (NB*TT)/128, 1), 128, SMEMB>>>(
        hb_h, hb_l, dw_h, dw_l, dense_b, out, nullptr, nullptr,
        UU, UU, UU, HH, 0, 0, 0);
}

// round 13
// speedup vs baseline: 1.4582x; 1.2035x over previous
#include <cuda_runtime.h>
#include <cuda_bf16.h>
#include <cuda_fp16.h>
#include <stdint.h>
#include <math.h>

#define NB 4
#define TT 2048
#define TI 2048
#define HH 1024
#define UU 4096

typedef __nv_bfloat16 bf16;
typedef __half f16;

// ---------------------------------------------------------------------------
// Scratch (allocation-free: __device__ globals)
// ---------------------------------------------------------------------------
__device__ bf16 g_te_h[(size_t)NB*TT*HH];
__device__ bf16 g_te_l[(size_t)NB*TT*HH];
__device__ bf16 g_ie_h[(size_t)NB*TI*HH];
__device__ bf16 g_ie_l[(size_t)NB*TI*HH];
__device__ bf16 g_ieT_h[(size_t)NB*HH*TI];
__device__ bf16 g_ieT_l[(size_t)NB*HH*TI];
__device__ float g_logits[(size_t)NB*TT*TI];
__device__ bf16 g_p_h[(size_t)NB*TT*TI];
__device__ bf16 g_p_l[(size_t)NB*TT*TI];
__device__ f16  g_at16_h[(size_t)NB*TT*HH];   // attn fp16 hi (for conv 2-term)
__device__ f16  g_at16_l[(size_t)NB*TT*HH];   // attn fp16 lo
__device__ bf16 g_hb_h[(size_t)NB*TT*UU];
__device__ bf16 g_hb_l[(size_t)NB*TT*UU];
__device__ f16  g_cwh[(size_t)UU*3*HH];       // conv weights fp16 hi only
__device__ bf16 g_dw_h[(size_t)HH*UU];
__device__ bf16 g_dw_l[(size_t)HH*UU];

// ---------------------------------------------------------------------------
// Helpers
// ---------------------------------------------------------------------------
__device__ __forceinline__ uint32_t cvta_smem(const void* p) {
    uint32_t a;
    asm("{ .reg .u64 t; cvta.to.shared.u64 t, %1; cvt.u32.u64 %0, t; }"
        : "=r"(a) : "l"(p));
    return a;
}
__device__ __forceinline__ void bsplit(float v, bf16& h, bf16& l) {
    h = __float2bfloat16(v);
    l = __float2bfloat16(v - __bfloat162float(h));
}
__device__ __forceinline__ void hsplit(float v, f16& h, f16& l) {
    h = __float2half(v);
    l = __float2half(v - __half2float(h));
}
__device__ __forceinline__ void cpa16(uint32_t d, const void* s) {
    asm volatile("cp.async.cg.shared.global [%0], [%1], 16;" :: "r"(d), "l"(s));
}
__device__ __forceinline__ void cpa16z(uint32_t d, const void* s, unsigned sz) {
    asm volatile("cp.async.cg.shared.global [%0], [%1], 16, %2;"
                 :: "r"(d), "l"(s), "r"(sz));
}
__device__ __forceinline__ void cpa_commit() {
    asm volatile("cp.async.commit_group;" ::: "memory");
}
template <int N>
__device__ __forceinline__ void cpa_wait() {
    asm volatile("cp.async.wait_group %0;" :: "n"(N) : "memory");
}
// SW64 swizzle: bits[4:5] ^= bits[7:8] (row stride 64B, conflict-free ldmatrix)
__device__ __forceinline__ uint32_t sw64(uint32_t o) {
    return o ^ ((o >> 3) & 0x30);
}

#define LDM4(f, a) \
    asm volatile("ldmatrix.sync.aligned.m8n8.x4.shared.b16 {%0,%1,%2,%3}, [%4];" \
        : "=r"((f)[0]), "=r"((f)[1]), "=r"((f)[2]), "=r"((f)[3]) : "r"(a))
#define MMA16816(d, a, b) \
    asm volatile("mma.sync.aligned.m16n8k16.row.col.f32.bf16.bf16.f32 " \
        "{%0,%1,%2,%3}, {%4,%5,%6,%7}, {%8,%9}, {%0,%1,%2,%3};" \
        : "+f"((d)[0]), "+f"((d)[1]), "+f"((d)[2]), "+f"((d)[3]) \
        : "r"((a)[0]), "r"((a)[1]), "r"((a)[2]), "r"((a)[3]), \
          "r"((b)[0]), "r"((b)[1]))
#define MMA16816H(d, a, b) \
    asm volatile("mma.sync.aligned.m16n8k16.row.col.f32.f16.f16.f32 " \
        "{%0,%1,%2,%3}, {%4,%5,%6,%7}, {%8,%9}, {%0,%1,%2,%3};" \
        : "+f"((d)[0]), "+f"((d)[1]), "+f"((d)[2]), "+f"((d)[3]) \
        : "r"((a)[0]), "r"((a)[1]), "r"((a)[2]), "r"((a)[3]), \
          "r"((b)[0]), "r"((b)[1]))

// ---------------------------------------------------------------------------
// Embedding gather + scale + bf16 hi/lo split
// ---------------------------------------------------------------------------
__global__ void gather_split(const int* __restrict__ idx, const float* __restrict__ emb,
                             bf16* __restrict__ oh, bf16* __restrict__ ol,
                             int n_tok, float scale) {
    int i = blockIdx.x * 256 + threadIdx.x;
    if (i >= n_tok * 256) return;
    int tok = i >> 8, h4 = i & 255;
    float4 v = ((const float4*)emb)[(size_t)idx[tok] * 256 + h4];
    float f[4] = {v.x * scale, v.y * scale, v.z * scale, v.w * scale};
    bf16 h[4], l[4];
    #pragma unroll
    for (int k = 0; k < 4; ++k) bsplit(f[k], h[k], l[k]);
    size_t o = (size_t)tok * HH + h4 * 4;
    __nv_bfloat162 a, b;
    a.x = h[0]; a.y = h[1]; b.x = h[2]; b.y = h[3];
    *(__nv_bfloat162*)(oh + o) = a; *(__nv_bfloat162*)(oh + o + 2) = b;
    a.x = l[0]; a.y = l[1]; b.x = l[2]; b.y = l[3];
    *(__nv_bfloat162*)(ol + o) = a; *(__nv_bfloat162*)(ol + o + 2) = b;
}

// ---------------------------------------------------------------------------
// bf16 transpose [R,C] -> [C,R]; z selects (batch, hi/lo plane)
// ---------------------------------------------------------------------------
__global__ void transpose_b2(const bf16* __restrict__ in0, bf16* __restrict__ out0,
                             const bf16* __restrict__ in1, bf16* __restrict__ out1,
                             int R, int C, int zsplit) {
    __shared__ bf16 t[32][33];
    int zz = blockIdx.z;
    const bf16* in;
    bf16* out;
    if (zz < zsplit) { in = in0 + (size_t)zz * R * C; out = out0 + (size_t)zz * R * C; }
    else { zz -= zsplit; in = in1 + (size_t)zz * R * C; out = out1 + (size_t)zz * R * C; }
    int c0 = blockIdx.x * 32, r0 = blockIdx.y * 32;
    for (int i = threadIdx.y; i < 32; i += 8)
        t[i][threadIdx.x] = in[(size_t)(r0 + i) * C + c0 + threadIdx.x];
    __syncthreads();
    for (int i = threadIdx.y; i < 32; i += 8)
        out[(size_t)(c0 + i) * R + r0 + threadIdx.x] = t[threadIdx.x][i];
}

// fp32 weight transpose [R,C] -> bf16 hi/lo [C,R]
__global__ void transpose_split_w(const float* __restrict__ in,
                                  bf16* __restrict__ oh, bf16* __restrict__ ol,
                                  int R, int C) {
    __shared__ float t[32][33];
    int c0 = blockIdx.x * 32, r0 = blockIdx.y * 32;
    for (int i = threadIdx.y; i < 32; i += 8)
        t[i][threadIdx.x] = in[(size_t)(r0 + i) * C + c0 + threadIdx.x];
    __syncthreads();
    for (int i = threadIdx.y; i < 32; i += 8) {
        bf16 h, l;
        bsplit(t[threadIdx.x][i], h, l);
        size_t o = (size_t)(c0 + i) * R + r0 + threadIdx.x;
        oh[o] = h; ol[o] = l;
    }
}

// fp32 weight transpose [R,C] -> fp16 (hi only) [C,R]
__global__ void transpose_w16(const float* __restrict__ in,
                              f16* __restrict__ oh, int R, int C) {
    __shared__ float t[32][33];
    int c0 = blockIdx.x * 32, r0 = blockIdx.y * 32;
    for (int i = threadIdx.y; i < 32; i += 8)
        t[i][threadIdx.x] = in[(size_t)(r0 + i) * C + c0 + threadIdx.x];
    __syncthreads();
    for (int i = threadIdx.y; i < 32; i += 8)
        oh[(size_t)(c0 + i) * R + r0 + threadIdx.x] = __float2half(t[threadIdx.x][i]);
}

// ---------------------------------------------------------------------------
// Softmax over TI cols, writes bf16 hi/lo probabilities
// ---------------------------------------------------------------------------
__global__ void softmax_split(const float* __restrict__ logits,
                              bf16* __restrict__ ph_, bf16* __restrict__ pl_) {
    __shared__ float red[256];
    const int tid = threadIdx.x;
    const float4* p = (const float4*)(logits + (size_t)blockIdx.x * TI);
    float4 v0 = p[tid];
    float4 v1 = p[tid + 256];

    float m = fmaxf(fmaxf(fmaxf(v0.x, v0.y), fmaxf(v0.z, v0.w)),
                    fmaxf(fmaxf(v1.x, v1.y), fmaxf(v1.z, v1.w)));
    red[tid] = m;
    __syncthreads();
    #pragma unroll
    for (int s = 128; s > 0; s >>= 1) {
        if (tid < s) red[tid] = fmaxf(red[tid], red[tid + s]);
        __syncthreads();
    }
    m = red[0];
    __syncthreads();

    v0.x = expf(v0.x - m); v0.y = expf(v0.y - m);
    v0.z = expf(v0.z - m); v0.w = expf(v0.w - m);
    v1.x = expf(v1.x - m); v1.y = expf(v1.y - m);
    v1.z = expf(v1.z - m); v1.w = expf(v1.w - m);

    red[tid] = v0.x + v0.y + v0.z + v0.w + v1.x + v1.y + v1.z + v1.w;
    __syncthreads();
    #pragma unroll
    for (int s = 128; s > 0; s >>= 1) {
        if (tid < s) red[tid] += red[tid + s];
        __syncthreads();
    }
    float inv = 1.f / red[0];

    size_t base = (size_t)blockIdx.x * TI;
    float f[8] = {v0.x*inv, v0.y*inv, v0.z*inv, v0.w*inv,
                  v1.x*inv, v1.y*inv, v1.z*inv, v1.w*inv};
    #pragma unroll
    for (int g = 0; g < 2; ++g) {
        size_t o = base + (size_t)(tid + g * 256) * 4;
        bf16 h[4], l[4];
        #pragma unroll
        for (int k = 0; k < 4; ++k) bsplit(f[g*4 + k], h[k], l[k]);
        __nv_bfloat162 a, b;
        a.x = h[0]; a.y = h[1]; b.x = h[2]; b.y = h[3];
        *(__nv_bfloat162*)(ph_ + o) = a; *(__nv_bfloat162*)(ph_ + o + 2) = b;
        a.x = l[0]; a.y = l[1]; b.x = l[2]; b.y = l[3];
        *(__nv_bfloat162*)(pl_ + o) = a; *(__nv_bfloat162*)(pl_ + o + 2) = b;
    }
}

// ---------------------------------------------------------------------------
// bf16x3 GEMM via mma.sync: 128x128 CTA tile, 4 warps (64x64 warp tile),
// BK=32, SW64 smem, 3-stage cp.async pipeline (R12 structure), 2 CTAs/SM.
// EPI: 0 fp32 | 2 +bias,relu,bf16 split | 3 +bias fp32 | 4 fp16 split
// ---------------------------------------------------------------------------
#define TILE_T 8192             // 128 rows * 64B (SW64 swizzled, no pad)
#define STAGE_B (4 * TILE_T)    // Ah, Al, Bh, Bl = 32768
#define NSTAGE 3

template <int EPI>
__global__ __launch_bounds__(128, 2)
void mma_gemm(const bf16* __restrict__ Ah_, const bf16* __restrict__ Al_,
              const bf16* __restrict__ Bh_, const bf16* __restrict__ Bl_,
              const float* __restrict__ bias,
              float* __restrict__ Cf, void* __restrict__ Ch_, void* __restrict__ Cl_,
              int K, int lda, int ldb, int ldc,
              size_t sA, size_t sB, size_t sC)
{
    extern __shared__ char smem[];
    const uint32_t sbase = cvta_smem(smem);
    const int tid  = threadIdx.x;
    const int lane = tid & 31;
    const int wid  = tid >> 5;
    const int wm   = wid & 1;
    const int wn   = wid >> 1;

    const size_t z = blockIdx.z;
    Ah_ += z * sA; Al_ += z * sA;
    Bh_ += z * sB; Bl_ += z * sB;
    if (Cf) Cf += z * sC;

    const int bm = blockIdx.y * 128;
    const int bn = blockIdx.x * 128;
    const int KT = K >> 5;

    float acc[4][8][4];
    #pragma unroll
    for (int a = 0; a < 4; ++a)
        #pragma unroll
        for (int b = 0; b < 8; ++b)
            #pragma unroll
            for (int c = 0; c < 4; ++c) acc[a][b][c] = 0.f;

    auto load_stage = [&](int slot, int kt) {
        const int k0 = kt * 32;
        const uint32_t sb = sbase + slot * STAGE_B;
        #pragma unroll
        for (int half = 0; half < 4; ++half) {
            const int idx = tid + half * 128;
            const int r = idx >> 2;
            const int c = idx & 3;
            const uint32_t so = sw64((uint32_t)(r * 64 + c * 16));
            cpa16(sb + so,              Ah_ + (size_t)(bm + r) * lda + k0 + c * 8);
            cpa16(sb + TILE_T + so,     Al_ + (size_t)(bm + r) * lda + k0 + c * 8);
            cpa16(sb + 2 * TILE_T + so, Bh_ + (size_t)(bn + r) * ldb + k0 + c * 8);
            cpa16(sb + 3 * TILE_T + so, Bl_ + (size_t)(bn + r) * ldb + k0 + c * 8);
        }
        cpa_commit();
    };

    auto compute_ks = [&](uint32_t sb, int ks) {
        const uint32_t sbB = sb + 2 * TILE_T;
        uint32_t Ahf[4][4], Alf[4][4];
        const int arow  = wm * 64 + (lane & 15);
        const int ahalf = lane >> 4;
        #pragma unroll
        for (int mf = 0; mf < 4; ++mf) {
            const uint32_t ao = sw64((uint32_t)((arow + mf * 16) * 64
                              + (ks * 2 + ahalf) * 16));
            LDM4(Ahf[mf], sb + ao);
            LDM4(Alf[mf], sb + TILE_T + ao);
        }
        const int bmat = lane >> 3;
        const int brow0 = wn * 64 + (lane & 7) + (bmat >> 1) * 8;
        const int bko = (ks * 2 + (bmat & 1)) * 16;
        #pragma unroll
        for (int np = 0; np < 4; ++np) {
            uint32_t Bhf[4], Blf[4];
            const uint32_t bo = sw64((uint32_t)((brow0 + np * 16) * 64 + bko));
            LDM4(Bhf, sbB + bo);
            LDM4(Blf, sbB + TILE_T + bo);
            #pragma unroll
            for (int sub = 0; sub < 2; ++sub)
                #pragma unroll
                for (int mf = 0; mf < 4; ++mf)
                    MMA16816(acc[mf][np * 2 + sub], Ahf[mf], &Bhf[sub * 2]);
            #pragma unroll
            for (int sub = 0; sub < 2; ++sub)
                #pragma unroll
                for (int mf = 0; mf < 4; ++mf)
                    MMA16816(acc[mf][np * 2 + sub], Ahf[mf], &Blf[sub * 2]);
            #pragma unroll
            for (int sub = 0; sub < 2; ++sub)
                #pragma unroll
                for (int mf = 0; mf < 4; ++mf)
                    MMA16816(acc[mf][np * 2 + sub], Alf[mf], &Bhf[sub * 2]);
        }
    };

    load_stage(0, 0);
    load_stage(1, 1);

    for (int kt = 0; kt < KT; ++kt) {
        if (kt + 1 < KT) cpa_wait<1>(); else cpa_wait<0>();
        __syncthreads();
        const uint32_t sb = sbase + (kt % NSTAGE) * STAGE_B;
        compute_ks(sb, 0);
        if (kt + 2 < KT) load_stage((kt + 2) % NSTAGE, kt + 2);
        compute_ks(sb, 1);
    }

    // ---- epilogue
    const int mrow = bm + wm * 64 + (lane >> 2);
    const int ncol = bn + wn * 64 + (lane & 3) * 2;
    #pragma unroll
    for (int mf = 0; mf < 4; ++mf) {
        #pragma unroll
        for (int nf = 0; nf < 8; ++nf) {
            const float* a4 = acc[mf][nf];
            #pragma unroll
            for (int h = 0; h < 2; ++h) {
                const int m = mrow + mf * 16 + h * 8;
                const int n = ncol + nf * 8;
                float v0 = a4[h * 2 + 0];
                float v1 = a4[h * 2 + 1];
                if (EPI == 0) {
                    *(float2*)(Cf + (size_t)m * ldc + n) = make_float2(v0, v1);
                } else if (EPI == 3) {
                    *(float2*)(Cf + (size_t)m * ldc + n) =
                        make_float2(v0 + bias[n], v1 + bias[n + 1]);
                } else if (EPI == 4) {
                    f16* dh = (f16*)Ch_ + z * sC;
                    f16* dl = (f16*)Cl_ + z * sC;
                    f16 h0, l0, h1, l1;
                    hsplit(v0, h0, l0);
                    hsplit(v1, h1, l1);
                    __half2 vh, vl;
                    vh.x = h0; vh.y = h1;
                    vl.x = l0; vl.y = l1;
                    *(__half2*)(dh + (size_t)m * ldc + n) = vh;
                    *(__half2*)(dl + (size_t)m * ldc + n) = vl;
                } else {
                    bf16* dh = (bf16*)Ch_ + z * sC;
                    bf16* dl = (bf16*)Cl_ + z * sC;
                    if (EPI == 2) {
                        v0 = fmaxf(v0 + bias[n], 0.f);
                        v1 = fmaxf(v1 + bias[n + 1], 0.f);
                    }
                    bf16 h0, l0, h1, l1;
                    bsplit(v0, h0, l0);
                    bsplit(v1, h1, l1);
                    __nv_bfloat162 vh, vl;
                    vh.x = h0; vh.y = h1;
                    vl.x = l0; vl.y = l1;
                    *(__nv_bfloat162*)(dh + (size_t)m * ldc + n) = vh;
                    *(__nv_bfloat162*)(dl + (size_t)m * ldc + n) = vl;
                }
            }
        }
    }
}

// ---------------------------------------------------------------------------
// Conv GEMM: fp16 2-term (A = attn fp16 hi/lo via implicit im2col, B = conv
// weight fp16 hi only). C = (Ah + Al) * Bh^T; +bias, relu, bf16-split out.
// Stage = Ah(8K) + Al(8K) + Bh(8K) = 24KB; 3 stages = 72KB; 2 CTAs/SM.
// ---------------------------------------------------------------------------
#define CSTAGE_B (3 * TILE_T)   // 24576

__global__ __launch_bounds__(128, 2)
void conv_gemm_h16(const f16* __restrict__ Ah_, const f16* __restrict__ Al_,
                   const f16* __restrict__ Bh_,
                   const float* __restrict__ bias,
                   bf16* __restrict__ Ch, bf16* __restrict__ Cl, int ldc)
{
    extern __shared__ char smem[];
    const uint32_t sbase = cvta_smem(smem);
    const int tid  = threadIdx.x;
    const int lane = tid & 31;
    const int wid  = tid >> 5;
    const int wm   = wid & 1;
    const int wn   = wid >> 1;

    const int bm = blockIdx.y * 128;
    const int bn = blockIdx.x * 128;
    const int KT = (3 * HH) >> 5;    // 96

    float acc[4][8][4];
    #pragma unroll
    for (int a = 0; a < 4; ++a)
        #pragma unroll
        for (int b = 0; b < 8; ++b)
            #pragma unroll
            for (int c = 0; c < 4; ++c) acc[a][b][c] = 0.f;

    auto load_stage = [&](int slot, int kt) {
        const int k0 = kt * 32;
        const uint32_t sb = sbase + slot * CSTAGE_B;
        const int tap = k0 >> 10;
        #pragma unroll
        for (int half = 0; half < 4; ++half) {
            const int idx = tid + half * 128;
            const int r = idx >> 2;
            const int c = idx & 3;
            const uint32_t so = sw64((uint32_t)(r * 64 + c * 16));
            // A im2col (fp16 hi/lo)
            const int ccol = (k0 & 1023) + c * 8;
            const int m = bm + r;
            const int b = m >> 11;
            const int t = (m & 2047) + tap - 1;
            const unsigned ok = ((unsigned)t < 2048u) ? 16u : 0u;
            const size_t o = ((size_t)b * 2048 + (ok ? t : 0)) * 1024 + ccol;
            cpa16z(sb + so,          Ah_ + o, ok);
            cpa16z(sb + TILE_T + so, Al_ + o, ok);
            // B hi only
            cpa16(sb + 2 * TILE_T + so,
                  Bh_ + (size_t)(bn + r) * (3 * HH) + k0 + c * 8);
        }
        cpa_commit();
    };

    auto compute_ks = [&](uint32_t sb, int ks) {
        const uint32_t sbB = sb + 2 * TILE_T;
        uint32_t Ahf[4][4], Alf[4][4];
        const int arow  = wm * 64 + (lane & 15);
        const int ahalf = lane >> 4;
        #pragma unroll
        for (int mf = 0; mf < 4; ++mf) {
            const uint32_t ao = sw64((uint32_t)((arow + mf * 16) * 64
                              + (ks * 2 + ahalf) * 16));
            LDM4(Ahf[mf], sb + ao);
            LDM4(Alf[mf], sb + TILE_T + ao);
        }
        const int bmat = lane >> 3;
        const int brow0 = wn * 64 + (lane & 7) + (bmat >> 1) * 8;
        const int bko = (ks * 2 + (bmat & 1)) * 16;
        #pragma unroll
        for (int np = 0; np < 4; ++np) {
            uint32_t Bhf[4];
            const uint32_t bo = sw64((uint32_t)((brow0 + np * 16) * 64 + bko));
            LDM4(Bhf, sbB + bo);
            // 2 terms, term-major: same-acc reuse distance = 8 MMAs
            #pragma unroll
            for (int sub = 0; sub < 2; ++sub)
                #pragma unroll
                for (int mf = 0; mf < 4; ++mf)
                    MMA16816H(acc[mf][np * 2 + sub], Ahf[mf], &Bhf[sub * 2]);
            #pragma unroll
            for (int sub = 0; sub < 2; ++sub)
                #pragma unroll
                for (int mf = 0; mf < 4; ++mf)
                    MMA16816H(acc[mf][np * 2 + sub], Alf[mf], &Bhf[sub * 2]);
        }
    };

    load_stage(0, 0);
    load_stage(1, 1);

    for (int kt = 0; kt < KT; ++kt) {
        if (kt + 1 < KT) cpa_wait<1>(); else cpa_wait<0>();
        __syncthreads();
        const uint32_t sb = sbase + (kt % NSTAGE) * CSTAGE_B;
        compute_ks(sb, 0);
        if (kt + 2 < KT) load_stage((kt + 2) % NSTAGE, kt + 2);
        compute_ks(sb, 1);
    }

    // ---- epilogue: +bias, relu, bf16 split
    const int mrow = bm + wm * 64 + (lane >> 2);
    const int ncol = bn + wn * 64 + (lane & 3) * 2;
    #pragma unroll
    for (int mf = 0; mf < 4; ++mf) {
        #pragma unroll
        for (int nf = 0; nf < 8; ++nf) {
            const float* a4 = acc[mf][nf];
            #pragma unroll
            for (int h = 0; h < 2; ++h) {
                const int m = mrow + mf * 16 + h * 8;
                const int n = ncol + nf * 8;
                float v0 = fmaxf(a4[h * 2 + 0] + bias[n], 0.f);
                float v1 = fmaxf(a4[h * 2 + 1] + bias[n + 1], 0.f);
                bf16 h0, l0, h1, l1;
                bsplit(v0, h0, l0);
                bsplit(v1, h1, l1);
                __nv_bfloat162 vh, vl;
                vh.x = h0; vh.y = h1;
                vl.x = l0; vl.y = l1;
                *(__nv_bfloat162*)(Ch + (size_t)m * ldc + n) = vh;
                *(__nv_bfloat162*)(Cl + (size_t)m * ldc + n) = vl;
            }
        }
    }
}

// ---------------------------------------------------------------------------
extern "C" void kernel_launch(void* const* d_in, const int* in_sizes, int n_in,
                              void* d_out, int out_size) {
    const int*   inputs     = (const int*)d_in[0];
    const int*   targets    = (const int*)d_in[1];
    const float* input_emb  = (const float*)d_in[2];
    const float* target_emb = (const float*)d_in[3];
    const float* conv_w     = (const float*)d_in[4];
    const float* conv_b     = (const float*)d_in[5];
    const float* dense_w    = (const float*)d_in[6];
    const float* dense_b    = (const float*)d_in[7];
    float* out = (float*)d_out;

    bf16 *te_h, *te_l, *ie_h, *ie_l, *ieT_h, *ieT_l, *p_h, *p_l;
    bf16 *hb_h, *hb_l, *dw_h, *dw_l;
    f16 *at16_h, *at16_l, *cwh;
    float* lg;
    cudaGetSymbolAddress((void**)&te_h, g_te_h);
    cudaGetSymbolAddress((void**)&te_l, g_te_l);
    cudaGetSymbolAddress((void**)&ie_h, g_ie_h);
    cudaGetSymbolAddress((void**)&ie_l, g_ie_l);
    cudaGetSymbolAddress((void**)&ieT_h, g_ieT_h);
    cudaGetSymbolAddress((void**)&ieT_l, g_ieT_l);
    cudaGetSymbolAddress((void**)&lg, g_logits);
    cudaGetSymbolAddress((void**)&p_h, g_p_h);
    cudaGetSymbolAddress((void**)&p_l, g_p_l);
    cudaGetSymbolAddress((void**)&at16_h, g_at16_h);
    cudaGetSymbolAddress((void**)&at16_l, g_at16_l);
    cudaGetSymbolAddress((void**)&hb_h, g_hb_h);
    cudaGetSymbolAddress((void**)&hb_l, g_hb_l);
    cudaGetSymbolAddress((void**)&cwh, g_cwh);
    cudaGetSymbolAddress((void**)&dw_h, g_dw_h);
    cudaGetSymbolAddress((void**)&dw_l, g_dw_l);

    const int SMEMB = NSTAGE * STAGE_B;     // 98304
    const int CSMEMB = NSTAGE * CSTAGE_B;   // 73728
    cudaFuncSetAttribute(mma_gemm<0>, cudaFuncAttributeMaxDynamicSharedMemorySize, SMEMB);
    cudaFuncSetAttribute(mma_gemm<4>, cudaFuncAttributeMaxDynamicSharedMemorySize, SMEMB);
    cudaFuncSetAttribute(mma_gemm<3>, cudaFuncAttributeMaxDynamicSharedMemorySize, SMEMB);
    cudaFuncSetAttribute(conv_gemm_h16, cudaFuncAttributeMaxDynamicSharedMemorySize, CSMEMB);

    // 1-2: gathers (te unscaled; ie carries the 32 factor)
    gather_split<<<NB * TT, 256>>>(targets, target_emb, te_h, te_l, NB * TT, 1.0f);
    gather_split<<<NB * TI, 256>>>(inputs, input_emb, ie_h, ie_l, NB * TI, 32.0f);

    // 3: fused ie hi+lo transpose (needs only ie)
    transpose_b2<<<dim3(HH/32, TI/32, 2*NB), dim3(32, 8)>>>(
        ie_h, ieT_h, ie_l, ieT_l, TI, HH, NB);

    // 4: logits = te @ (ie*32)^T   [B, TT, TI]   <-- PROFILED LAUNCH
    mma_gemm<0><<<dim3(TI/128, TT/128, NB), 128, SMEMB>>>(
        te_h, te_l, ie_h, ie_l, nullptr, lg, nullptr, nullptr,
        HH, HH, HH, TI, (size_t)TT*HH, (size_t)TI*HH, (size_t)TT*TI);

    // 5-6: weight transposes (needed only by G3/G4)
    transpose_w16<<<dim3(UU/32, (3*HH)/32), dim3(32, 8)>>>(conv_w, cwh, 3*HH, UU);
    transpose_split_w<<<dim3(HH/32, UU/32), dim3(32, 8)>>>(dense_w, dw_h, dw_l, UU, HH);

    // 7: softmax -> prob splits
    softmax_split<<<NB * TT, 256>>>(lg, p_h, p_l);

    // 8: attn = P @ ie   [B, TT, HH] -> fp16 hi/lo splits (for conv 2-term)
    mma_gemm<4><<<dim3(HH/128, TT/128, NB), 128, SMEMB>>>(
        p_h, p_l, ieT_h, ieT_l, nullptr, nullptr, at16_h, at16_l,
        TI, TI, TI, HH, (size_t)TT*TI, (size_t)HH*TI, (size_t)TT*HH);

    // 9: h = relu(conv1d(attn) + conv_b)   [8192, UU], fp16 2-term im2col GEMM
    conv_gemm_h16<<<dim3(UU/128, (NB*TT)/128, 1), 128, CSMEMB>>>(
        at16_h, at16_l, cwh, conv_b, hb_h, hb_l, UU);

    // 10: out = h @ dense_w + dense_b   [8192, HH], bf16 3-term
    mma_gemm<3><<<dim3(HH/128, (NB*TT)/128, 1), 128, SMEMB>>>(
        hb_h, hb_l, dw_h, dw_l, dense_b, out, nullptr, nullptr,
        UU, UU, UU, HH, 0, 0, 0);
}

// round 14
// speedup vs baseline: 1.7587x; 1.2061x over previous
#include <cuda_runtime.h>
#include <cuda_bf16.h>
#include <cuda_fp16.h>
#include <stdint.h>
#include <math.h>

#define NB 4
#define TT 2048
#define TI 2048
#define HH 1024
#define UU 4096

typedef __half f16;

// ---------------------------------------------------------------------------
// Scratch (allocation-free: __device__ globals), all fp16 operand planes
// ---------------------------------------------------------------------------
__device__ f16  g_te_h[(size_t)NB*TT*HH];
__device__ f16  g_te_l[(size_t)NB*TT*HH];
__device__ f16  g_ie_h[(size_t)NB*TI*HH];     // hi only (B operand of G1)
__device__ f16  g_ieT[(size_t)NB*HH*TI];      // hi only (B operand of G2)
__device__ float g_logits[(size_t)NB*TT*TI];
__device__ f16  g_p_h[(size_t)NB*TT*TI];
__device__ f16  g_p_l[(size_t)NB*TT*TI];
__device__ f16  g_at_h[(size_t)NB*TT*HH];
__device__ f16  g_at_l[(size_t)NB*TT*HH];
__device__ f16  g_hb_h[(size_t)NB*TT*UU];
__device__ f16  g_hb_l[(size_t)NB*TT*UU];
__device__ f16  g_cwh[(size_t)UU*3*HH];       // conv weights fp16 hi only
__device__ f16  g_dwh[(size_t)HH*UU];         // dense weights fp16 hi only

// ---------------------------------------------------------------------------
// Helpers
// ---------------------------------------------------------------------------
__device__ __forceinline__ uint32_t cvta_smem(const void* p) {
    uint32_t a;
    asm("{ .reg .u64 t; cvta.to.shared.u64 t, %1; cvt.u32.u64 %0, t; }"
        : "=r"(a) : "l"(p));
    return a;
}
__device__ __forceinline__ void hsplit(float v, f16& h, f16& l) {
    h = __float2half(v);
    l = __float2half(v - __half2float(h));
}
__device__ __forceinline__ void cpa16(uint32_t d, const void* s) {
    asm volatile("cp.async.cg.shared.global [%0], [%1], 16;" :: "r"(d), "l"(s));
}
__device__ __forceinline__ void cpa16z(uint32_t d, const void* s, unsigned sz) {
    asm volatile("cp.async.cg.shared.global [%0], [%1], 16, %2;"
                 :: "r"(d), "l"(s), "r"(sz));
}
__device__ __forceinline__ void cpa_commit() {
    asm volatile("cp.async.commit_group;" ::: "memory");
}
template <int N>
__device__ __forceinline__ void cpa_wait() {
    asm volatile("cp.async.wait_group %0;" :: "n"(N) : "memory");
}
// SW64 swizzle: bits[4:5] ^= bits[7:8]
__device__ __forceinline__ uint32_t sw64(uint32_t o) {
    return o ^ ((o >> 3) & 0x30);
}

#define LDM4(f, a) \
    asm volatile("ldmatrix.sync.aligned.m8n8.x4.shared.b16 {%0,%1,%2,%3}, [%4];" \
        : "=r"((f)[0]), "=r"((f)[1]), "=r"((f)[2]), "=r"((f)[3]) : "r"(a))
#define MMA16816H(d, a, b) \
    asm volatile("mma.sync.aligned.m16n8k16.row.col.f32.f16.f16.f32 " \
        "{%0,%1,%2,%3}, {%4,%5,%6,%7}, {%8,%9}, {%0,%1,%2,%3};" \
        : "+f"((d)[0]), "+f"((d)[1]), "+f"((d)[2]), "+f"((d)[3]) \
        : "r"((a)[0]), "r"((a)[1]), "r"((a)[2]), "r"((a)[3]), \
          "r"((b)[0]), "r"((b)[1]))

// ---------------------------------------------------------------------------
// Embedding gather + scale + fp16 hi/lo split
// ---------------------------------------------------------------------------
__global__ void gather_split16(const int* __restrict__ idx, const float* __restrict__ emb,
                               f16* __restrict__ oh, f16* __restrict__ ol,
                               int n_tok, float scale) {
    int i = blockIdx.x * 256 + threadIdx.x;
    if (i >= n_tok * 256) return;
    int tok = i >> 8, h4 = i & 255;
    float4 v = ((const float4*)emb)[(size_t)idx[tok] * 256 + h4];
    float f[4] = {v.x * scale, v.y * scale, v.z * scale, v.w * scale};
    f16 h[4], l[4];
    #pragma unroll
    for (int k = 0; k < 4; ++k) hsplit(f[k], h[k], l[k]);
    size_t o = (size_t)tok * HH + h4 * 4;
    __half2 a, b;
    a.x = h[0]; a.y = h[1]; b.x = h[2]; b.y = h[3];
    *(__half2*)(oh + o) = a; *(__half2*)(oh + o + 2) = b;
    if (ol) {
        a.x = l[0]; a.y = l[1]; b.x = l[2]; b.y = l[3];
        *(__half2*)(ol + o) = a; *(__half2*)(ol + o + 2) = b;
    }
}

// ---------------------------------------------------------------------------
// fp16 transpose [R,C] -> [C,R], z batches
// ---------------------------------------------------------------------------
__global__ void transpose_h16(const f16* __restrict__ in, f16* __restrict__ out,
                              int R, int C) {
    __shared__ f16 t[32][33];
    in  += (size_t)blockIdx.z * R * C;
    out += (size_t)blockIdx.z * R * C;
    int c0 = blockIdx.x * 32, r0 = blockIdx.y * 32;
    for (int i = threadIdx.y; i < 32; i += 8)
        t[i][threadIdx.x] = in[(size_t)(r0 + i) * C + c0 + threadIdx.x];
    __syncthreads();
    for (int i = threadIdx.y; i < 32; i += 8)
        out[(size_t)(c0 + i) * R + r0 + threadIdx.x] = t[threadIdx.x][i];
}

// fp32 weight transpose [R,C] -> fp16 (hi only) [C,R]
__global__ void transpose_w16(const float* __restrict__ in,
                              f16* __restrict__ oh, int R, int C) {
    __shared__ float t[32][33];
    int c0 = blockIdx.x * 32, r0 = blockIdx.y * 32;
    for (int i = threadIdx.y; i < 32; i += 8)
        t[i][threadIdx.x] = in[(size_t)(r0 + i) * C + c0 + threadIdx.x];
    __syncthreads();
    for (int i = threadIdx.y; i < 32; i += 8)
        oh[(size_t)(c0 + i) * R + r0 + threadIdx.x] = __float2half(t[threadIdx.x][i]);
}

// ---------------------------------------------------------------------------
// Softmax over TI cols, writes fp16 hi/lo probabilities
// ---------------------------------------------------------------------------
__global__ void softmax_split16(const float* __restrict__ logits,
                                f16* __restrict__ ph_, f16* __restrict__ pl_) {
    __shared__ float red[256];
    const int tid = threadIdx.x;
    const float4* p = (const float4*)(logits + (size_t)blockIdx.x * TI);
    float4 v0 = p[tid];
    float4 v1 = p[tid + 256];

    float m = fmaxf(fmaxf(fmaxf(v0.x, v0.y), fmaxf(v0.z, v0.w)),
                    fmaxf(fmaxf(v1.x, v1.y), fmaxf(v1.z, v1.w)));
    red[tid] = m;
    __syncthreads();
    #pragma unroll
    for (int s = 128; s > 0; s >>= 1) {
        if (tid < s) red[tid] = fmaxf(red[tid], red[tid + s]);
        __syncthreads();
    }
    m = red[0];
    __syncthreads();

    v0.x = expf(v0.x - m); v0.y = expf(v0.y - m);
    v0.z = expf(v0.z - m); v0.w = expf(v0.w - m);
    v1.x = expf(v1.x - m); v1.y = expf(v1.y - m);
    v1.z = expf(v1.z - m); v1.w = expf(v1.w - m);

    red[tid] = v0.x + v0.y + v0.z + v0.w + v1.x + v1.y + v1.z + v1.w;
    __syncthreads();
    #pragma unroll
    for (int s = 128; s > 0; s >>= 1) {
        if (tid < s) red[tid] += red[tid + s];
        __syncthreads();
    }
    float inv = 1.f / red[0];

    size_t base = (size_t)blockIdx.x * TI;
    float f[8] = {v0.x*inv, v0.y*inv, v0.z*inv, v0.w*inv,
                  v1.x*inv, v1.y*inv, v1.z*inv, v1.w*inv};
    #pragma unroll
    for (int g = 0; g < 2; ++g) {
        size_t o = base + (size_t)(tid + g * 256) * 4;
        f16 h[4], l[4];
        #pragma unroll
        for (int k = 0; k < 4; ++k) hsplit(f[g*4 + k], h[k], l[k]);
        __half2 a, b;
        a.x = h[0]; a.y = h[1]; b.x = h[2]; b.y = h[3];
        *(__half2*)(ph_ + o) = a; *(__half2*)(ph_ + o + 2) = b;
        a.x = l[0]; a.y = l[1]; b.x = l[2]; b.y = l[3];
        *(__half2*)(pl_ + o) = a; *(__half2*)(pl_ + o + 2) = b;
    }
}

// ---------------------------------------------------------------------------
// Universal fp16 2-term GEMM: C = (Ah + Al) * Bh^T (+ epilogue).
// 128x128 CTA tile, 4 warps (64x64 warp tile), BK=32, SW64 smem,
// 3-stage cp.async pipeline (R12 structure), 2 CTAs/SM.
// Stage = Ah(8K) + Al(8K) + Bh(8K) = 24KB.
// AMODE: 0 plain row-major A, 1 implicit im2col over attn (conv K=3 SAME)
// EPI:   0 fp32 | 1 fp16 split | 2 +bias,relu,fp16 split | 3 +bias fp32
// ---------------------------------------------------------------------------
#define TILE_T 8192             // 128 rows * 64B
#define STAGE_B (3 * TILE_T)    // 24576
#define NSTAGE 3

template <int AMODE, int EPI>
__global__ __launch_bounds__(128, 2)
void h16_gemm(const f16* __restrict__ Ah_, const f16* __restrict__ Al_,
              const f16* __restrict__ Bh_,
              const float* __restrict__ bias,
              float* __restrict__ Cf, f16* __restrict__ Ch, f16* __restrict__ Cl,
              int K, int lda, int ldb, int ldc,
              size_t sA, size_t sB, size_t sC)
{
    extern __shared__ char smem[];
    const uint32_t sbase = cvta_smem(smem);
    const int tid  = threadIdx.x;
    const int lane = tid & 31;
    const int wid  = tid >> 5;
    const int wm   = wid & 1;
    const int wn   = wid >> 1;

    const size_t z = blockIdx.z;
    Ah_ += z * sA; Al_ += z * sA;
    Bh_ += z * sB;
    if (Cf) Cf += z * sC;
    if (Ch) { Ch += z * sC; Cl += z * sC; }

    const int bm = blockIdx.y * 128;
    const int bn = blockIdx.x * 128;
    const int KT = K >> 5;

    float acc[4][8][4];
    #pragma unroll
    for (int a = 0; a < 4; ++a)
        #pragma unroll
        for (int b = 0; b < 8; ++b)
            #pragma unroll
            for (int c = 0; c < 4; ++c) acc[a][b][c] = 0.f;

    auto load_stage = [&](int slot, int kt) {
        const int k0 = kt * 32;
        const uint32_t sb = sbase + slot * STAGE_B;
        #pragma unroll
        for (int half = 0; half < 4; ++half) {
            const int idx = tid + half * 128;
            const int r = idx >> 2;
            const int c = idx & 3;
            const uint32_t so = sw64((uint32_t)(r * 64 + c * 16));
            if (AMODE == 0) {
                cpa16(sb + so,          Ah_ + (size_t)(bm + r) * lda + k0 + c * 8);
                cpa16(sb + TILE_T + so, Al_ + (size_t)(bm + r) * lda + k0 + c * 8);
            } else {
                const int tap = k0 >> 10;
                const int ccol = (k0 & 1023) + c * 8;
                const int m = bm + r;
                const int b = m >> 11;
                const int t = (m & 2047) + tap - 1;
                const unsigned ok = ((unsigned)t < 2048u) ? 16u : 0u;
                const size_t o = ((size_t)b * 2048 + (ok ? t : 0)) * 1024 + ccol;
                cpa16z(sb + so,          Ah_ + o, ok);
                cpa16z(sb + TILE_T + so, Al_ + o, ok);
            }
            cpa16(sb + 2 * TILE_T + so, Bh_ + (size_t)(bn + r) * ldb + k0 + c * 8);
        }
        cpa_commit();
    };

    auto compute_ks = [&](uint32_t sb, int ks) {
        const uint32_t sbB = sb + 2 * TILE_T;
        uint32_t Ahf[4][4], Alf[4][4];
        const int arow  = wm * 64 + (lane & 15);
        const int ahalf = lane >> 4;
        #pragma unroll
        for (int mf = 0; mf < 4; ++mf) {
            const uint32_t ao = sw64((uint32_t)((arow + mf * 16) * 64
                              + (ks * 2 + ahalf) * 16));
            LDM4(Ahf[mf], sb + ao);
            LDM4(Alf[mf], sb + TILE_T + ao);
        }
        const int bmat = lane >> 3;
        const int brow0 = wn * 64 + (lane & 7) + (bmat >> 1) * 8;
        const int bko = (ks * 2 + (bmat & 1)) * 16;
        #pragma unroll
        for (int np = 0; np < 4; ++np) {
            uint32_t Bhf[4];
            const uint32_t bo = sw64((uint32_t)((brow0 + np * 16) * 64 + bko));
            LDM4(Bhf, sbB + bo);
            // 2 terms, term-major across both n-subtiles: same-acc reuse = 8
            #pragma unroll
            for (int sub = 0; sub < 2; ++sub)
                #pragma unroll
                for (int mf = 0; mf < 4; ++mf)
                    MMA16816H(acc[mf][np * 2 + sub], Ahf[mf], &Bhf[sub * 2]);
            #pragma unroll
            for (int sub = 0; sub < 2; ++sub)
                #pragma unroll
                for (int mf = 0; mf < 4; ++mf)
                    MMA16816H(acc[mf][np * 2 + sub], Alf[mf], &Bhf[sub * 2]);
        }
    };

    load_stage(0, 0);
    load_stage(1, 1);

    for (int kt = 0; kt < KT; ++kt) {
        if (kt + 1 < KT) cpa_wait<1>(); else cpa_wait<0>();
        __syncthreads();
        const uint32_t sb = sbase + (kt % NSTAGE) * STAGE_B;
        compute_ks(sb, 0);
        if (kt + 2 < KT) load_stage((kt + 2) % NSTAGE, kt + 2);
        compute_ks(sb, 1);
    }

    // ---- epilogue
    const int mrow = bm + wm * 64 + (lane >> 2);
    const int ncol = bn + wn * 64 + (lane & 3) * 2;
    #pragma unroll
    for (int mf = 0; mf < 4; ++mf) {
        #pragma unroll
        for (int nf = 0; nf < 8; ++nf) {
            const float* a4 = acc[mf][nf];
            #pragma unroll
            for (int h = 0; h < 2; ++h) {
                const int m = mrow + mf * 16 + h * 8;
                const int n = ncol + nf * 8;
                float v0 = a4[h * 2 + 0];
                float v1 = a4[h * 2 + 1];
                if (EPI == 0) {
                    *(float2*)(Cf + (size_t)m * ldc + n) = make_float2(v0, v1);
                } else if (EPI == 3) {
                    *(float2*)(Cf + (size_t)m * ldc + n) =
                        make_float2(v0 + bias[n], v1 + bias[n + 1]);
                } else {
                    if (EPI == 2) {
                        v0 = fmaxf(v0 + bias[n], 0.f);
                        v1 = fmaxf(v1 + bias[n + 1], 0.f);
                    }
                    f16 h0, l0, h1, l1;
                    hsplit(v0, h0, l0);
                    hsplit(v1, h1, l1);
                    __half2 vh, vl;
                    vh.x = h0; vh.y = h1;
                    vl.x = l0; vl.y = l1;
                    *(__half2*)(Ch + (size_t)m * ldc + n) = vh;
                    *(__half2*)(Cl + (size_t)m * ldc + n) = vl;
                }
            }
        }
    }
}

// ---------------------------------------------------------------------------
extern "C" void kernel_launch(void* const* d_in, const int* in_sizes, int n_in,
                              void* d_out, int out_size) {
    const int*   inputs     = (const int*)d_in[0];
    const int*   targets    = (const int*)d_in[1];
    const float* input_emb  = (const float*)d_in[2];
    const float* target_emb = (const float*)d_in[3];
    const float* conv_w     = (const float*)d_in[4];
    const float* conv_b     = (const float*)d_in[5];
    const float* dense_w    = (const float*)d_in[6];
    const float* dense_b    = (const float*)d_in[7];
    float* out = (float*)d_out;

    f16 *te_h, *te_l, *ie_h, *ieT, *p_h, *p_l, *at_h, *at_l, *hb_h, *hb_l, *cwh, *dwh;
    float* lg;
    cudaGetSymbolAddress((void**)&te_h, g_te_h);
    cudaGetSymbolAddress((void**)&te_l, g_te_l);
    cudaGetSymbolAddress((void**)&ie_h, g_ie_h);
    cudaGetSymbolAddress((void**)&ieT, g_ieT);
    cudaGetSymbolAddress((void**)&lg, g_logits);
    cudaGetSymbolAddress((void**)&p_h, g_p_h);
    cudaGetSymbolAddress((void**)&p_l, g_p_l);
    cudaGetSymbolAddress((void**)&at_h, g_at_h);
    cudaGetSymbolAddress((void**)&at_l, g_at_l);
    cudaGetSymbolAddress((void**)&hb_h, g_hb_h);
    cudaGetSymbolAddress((void**)&hb_l, g_hb_l);
    cudaGetSymbolAddress((void**)&cwh, g_cwh);
    cudaGetSymbolAddress((void**)&dwh, g_dwh);

    const int SMEMB = NSTAGE * STAGE_B;   // 73728 -> 2 CTAs/SM
    cudaFuncSetAttribute(h16_gemm<0,0>, cudaFuncAttributeMaxDynamicSharedMemorySize, SMEMB);
    cudaFuncSetAttribute(h16_gemm<0,1>, cudaFuncAttributeMaxDynamicSharedMemorySize, SMEMB);
    cudaFuncSetAttribute(h16_gemm<1,2>, cudaFuncAttributeMaxDynamicSharedMemorySize, SMEMB);
    cudaFuncSetAttribute(h16_gemm<0,3>, cudaFuncAttributeMaxDynamicSharedMemorySize, SMEMB);

    // 1-2: gathers (te unscaled hi/lo; ie carries the 32 factor, hi only)
    gather_split16<<<NB * TT, 256>>>(targets, target_emb, te_h, te_l, NB * TT, 1.0f);
    gather_split16<<<NB * TI, 256>>>(inputs, input_emb, ie_h, nullptr, NB * TI, 32.0f);

    // 3: ieT = ie^T (hi only)
    transpose_h16<<<dim3(HH/32, TI/32, NB), dim3(32, 8)>>>(ie_h, ieT, TI, HH);

    // 4: logits = (te_h+te_l) @ ie_h^T   [B, TT, TI]   <-- PROFILED LAUNCH
    h16_gemm<0,0><<<dim3(TI/128, TT/128, NB), 128, SMEMB>>>(
        te_h, te_l, ie_h, nullptr, lg, nullptr, nullptr,
        HH, HH, HH, TI, (size_t)TT*HH, (size_t)TI*HH, (size_t)TT*TI);

    // 5-6: weight transposes (hi only)
    transpose_w16<<<dim3(UU/32, (3*HH)/32), dim3(32, 8)>>>(conv_w, cwh, 3*HH, UU);
    transpose_w16<<<dim3(HH/32, UU/32), dim3(32, 8)>>>(dense_w, dwh, UU, HH);

    // 7: softmax -> fp16 prob splits
    softmax_split16<<<NB * TT, 256>>>(lg, p_h, p_l);

    // 8: attn = (P_h+P_l) @ ieT^T   [B, TT, HH] -> fp16 splits
    h16_gemm<0,1><<<dim3(HH/128, TT/128, NB), 128, SMEMB>>>(
        p_h, p_l, ieT, nullptr, nullptr, at_h, at_l,
        TI, TI, TI, HH, (size_t)TT*TI, (size_t)HH*TI, (size_t)TT*HH);

    // 9: h = relu(conv1d(attn) + conv_b)   [8192, UU], im2col, fp16 splits out
    h16_gemm<1,2><<<dim3(UU/128, (NB*TT)/128, 1), 128, SMEMB>>>(
        at_h, at_l, cwh, conv_b, nullptr, hb_h, hb_l,
        3*HH, 0, 3*HH, UU, 0, 0, 0);

    // 10: out = (h_h+h_l) @ dense_w^T + dense_b   [8192, HH]
    h16_gemm<0,3><<<dim3(HH/128, (NB*TT)/128, 1), 128, SMEMB>>>(
        hb_h, hb_l, dwh, dense_b, out, nullptr, nullptr,
        UU, UU, UU, HH, 0, 0, 0);
}

// round 15
// speedup vs baseline: 1.7639x; 1.0030x over previous
#include <cuda_runtime.h>
#include <cuda_bf16.h>
#include <cuda_fp16.h>
#include <stdint.h>
#include <math.h>

#define NB 4
#define TT 2048
#define TI 2048
#define HH 1024
#define UU 4096

typedef __half f16;

// ---------------------------------------------------------------------------
// Scratch (allocation-free: __device__ globals), all fp16 operand planes
// ---------------------------------------------------------------------------
__device__ f16  g_te_h[(size_t)NB*TT*HH];
__device__ f16  g_te_l[(size_t)NB*TT*HH];
__device__ f16  g_ie_h[(size_t)NB*TI*HH];     // hi only (B operand of G1)
__device__ f16  g_ieT[(size_t)NB*HH*TI];      // hi only (B operand of G2)
__device__ float g_logits[(size_t)NB*TT*TI];
__device__ f16  g_p_h[(size_t)NB*TT*TI];
__device__ f16  g_p_l[(size_t)NB*TT*TI];
__device__ f16  g_at_h[(size_t)NB*TT*HH];
__device__ f16  g_at_l[(size_t)NB*TT*HH];
__device__ f16  g_hb_h[(size_t)NB*TT*UU];
__device__ f16  g_hb_l[(size_t)NB*TT*UU];
__device__ f16  g_cwh[(size_t)UU*3*HH];       // conv weights fp16 hi only
__device__ f16  g_dwh[(size_t)HH*UU];         // dense weights fp16 hi only

// ---------------------------------------------------------------------------
// Helpers
// ---------------------------------------------------------------------------
__device__ __forceinline__ uint32_t cvta_smem(const void* p) {
    uint32_t a;
    asm("{ .reg .u64 t; cvta.to.shared.u64 t, %1; cvt.u32.u64 %0, t; }"
        : "=r"(a) : "l"(p));
    return a;
}
__device__ __forceinline__ void hsplit(float v, f16& h, f16& l) {
    h = __float2half(v);
    l = __float2half(v - __half2float(h));
}
__device__ __forceinline__ void cpa16(uint32_t d, const void* s) {
    asm volatile("cp.async.cg.shared.global [%0], [%1], 16;" :: "r"(d), "l"(s));
}
__device__ __forceinline__ void cpa16z(uint32_t d, const void* s, unsigned sz) {
    asm volatile("cp.async.cg.shared.global [%0], [%1], 16, %2;"
                 :: "r"(d), "l"(s), "r"(sz));
}
__device__ __forceinline__ void cpa_commit() {
    asm volatile("cp.async.commit_group;" ::: "memory");
}
template <int N>
__device__ __forceinline__ void cpa_wait() {
    asm volatile("cp.async.wait_group %0;" :: "n"(N) : "memory");
}
// SW64 swizzle: bits[4:5] ^= bits[7:8]
__device__ __forceinline__ uint32_t sw64(uint32_t o) {
    return o ^ ((o >> 3) & 0x30);
}

#define LDM4(f, a) \
    asm volatile("ldmatrix.sync.aligned.m8n8.x4.shared.b16 {%0,%1,%2,%3}, [%4];" \
        : "=r"((f)[0]), "=r"((f)[1]), "=r"((f)[2]), "=r"((f)[3]) : "r"(a))
#define MMA16816H(d, a, b) \
    asm volatile("mma.sync.aligned.m16n8k16.row.col.f32.f16.f16.f32 " \
        "{%0,%1,%2,%3}, {%4,%5,%6,%7}, {%8,%9}, {%0,%1,%2,%3};" \
        : "+f"((d)[0]), "+f"((d)[1]), "+f"((d)[2]), "+f"((d)[3]) \
        : "r"((a)[0]), "r"((a)[1]), "r"((a)[2]), "r"((a)[3]), \
          "r"((b)[0]), "r"((b)[1]))

// ---------------------------------------------------------------------------
// Embedding gather + scale + fp16 hi/lo split
// ---------------------------------------------------------------------------
__global__ void gather_split16(const int* __restrict__ idx, const float* __restrict__ emb,
                               f16* __restrict__ oh, f16* __restrict__ ol,
                               int n_tok, float scale) {
    int i = blockIdx.x * 256 + threadIdx.x;
    if (i >= n_tok * 256) return;
    int tok = i >> 8, h4 = i & 255;
    float4 v = ((const float4*)emb)[(size_t)idx[tok] * 256 + h4];
    float f[4] = {v.x * scale, v.y * scale, v.z * scale, v.w * scale};
    f16 h[4], l[4];
    #pragma unroll
    for (int k = 0; k < 4; ++k) hsplit(f[k], h[k], l[k]);
    size_t o = (size_t)tok * HH + h4 * 4;
    __half2 a, b;
    a.x = h[0]; a.y = h[1]; b.x = h[2]; b.y = h[3];
    *(__half2*)(oh + o) = a; *(__half2*)(oh + o + 2) = b;
    if (ol) {
        a.x = l[0]; a.y = l[1]; b.x = l[2]; b.y = l[3];
        *(__half2*)(ol + o) = a; *(__half2*)(ol + o + 2) = b;
    }
}

// ---------------------------------------------------------------------------
// fp16 transpose [R,C] -> [C,R], z batches
// ---------------------------------------------------------------------------
__global__ void transpose_h16(const f16* __restrict__ in, f16* __restrict__ out,
                              int R, int C) {
    __shared__ f16 t[32][33];
    in  += (size_t)blockIdx.z * R * C;
    out += (size_t)blockIdx.z * R * C;
    int c0 = blockIdx.x * 32, r0 = blockIdx.y * 32;
    for (int i = threadIdx.y; i < 32; i += 8)
        t[i][threadIdx.x] = in[(size_t)(r0 + i) * C + c0 + threadIdx.x];
    __syncthreads();
    for (int i = threadIdx.y; i < 32; i += 8)
        out[(size_t)(c0 + i) * R + r0 + threadIdx.x] = t[threadIdx.x][i];
}

// fp32 weight transpose [R,C] -> fp16 (hi only) [C,R]
__global__ void transpose_w16(const float* __restrict__ in,
                              f16* __restrict__ oh, int R, int C) {
    __shared__ float t[32][33];
    int c0 = blockIdx.x * 32, r0 = blockIdx.y * 32;
    for (int i = threadIdx.y; i < 32; i += 8)
        t[i][threadIdx.x] = in[(size_t)(r0 + i) * C + c0 + threadIdx.x];
    __syncthreads();
    for (int i = threadIdx.y; i < 32; i += 8)
        oh[(size_t)(c0 + i) * R + r0 + threadIdx.x] = __float2half(t[threadIdx.x][i]);
}

// ---------------------------------------------------------------------------
// Softmax over TI cols, writes fp16 hi/lo probabilities
// ---------------------------------------------------------------------------
__global__ void softmax_split16(const float* __restrict__ logits,
                                f16* __restrict__ ph_, f16* __restrict__ pl_) {
    __shared__ float red[256];
    const int tid = threadIdx.x;
    const float4* p = (const float4*)(logits + (size_t)blockIdx.x * TI);
    float4 v0 = p[tid];
    float4 v1 = p[tid + 256];

    float m = fmaxf(fmaxf(fmaxf(v0.x, v0.y), fmaxf(v0.z, v0.w)),
                    fmaxf(fmaxf(v1.x, v1.y), fmaxf(v1.z, v1.w)));
    red[tid] = m;
    __syncthreads();
    #pragma unroll
    for (int s = 128; s > 0; s >>= 1) {
        if (tid < s) red[tid] = fmaxf(red[tid], red[tid + s]);
        __syncthreads();
    }
    m = red[0];
    __syncthreads();

    v0.x = expf(v0.x - m); v0.y = expf(v0.y - m);
    v0.z = expf(v0.z - m); v0.w = expf(v0.w - m);
    v1.x = expf(v1.x - m); v1.y = expf(v1.y - m);
    v1.z = expf(v1.z - m); v1.w = expf(v1.w - m);

    red[tid] = v0.x + v0.y + v0.z + v0.w + v1.x + v1.y + v1.z + v1.w;
    __syncthreads();
    #pragma unroll
    for (int s = 128; s > 0; s >>= 1) {
        if (tid < s) red[tid] += red[tid + s];
        __syncthreads();
    }
    float inv = 1.f / red[0];

    size_t base = (size_t)blockIdx.x * TI;
    float f[8] = {v0.x*inv, v0.y*inv, v0.z*inv, v0.w*inv,
                  v1.x*inv, v1.y*inv, v1.z*inv, v1.w*inv};
    #pragma unroll
    for (int g = 0; g < 2; ++g) {
        size_t o = base + (size_t)(tid + g * 256) * 4;
        f16 h[4], l[4];
        #pragma unroll
        for (int k = 0; k < 4; ++k) hsplit(f[g*4 + k], h[k], l[k]);
        __half2 a, b;
        a.x = h[0]; a.y = h[1]; b.x = h[2]; b.y = h[3];
        *(__half2*)(ph_ + o) = a; *(__half2*)(ph_ + o + 2) = b;
        a.x = l[0]; a.y = l[1]; b.x = l[2]; b.y = l[3];
        *(__half2*)(pl_ + o) = a; *(__half2*)(pl_ + o + 2) = b;
    }
}

// ---------------------------------------------------------------------------
// Universal fp16 2-term GEMM: C = (Ah + Al) * Bh^T (+ epilogue).
// 128x128 CTA tile, 4 warps (64x64 warp tile), BK=32, SW64 smem,
// FOUR-stage cp.async pipeline (each load gets ~3 kt of landing slack),
// 2 CTAs/SM (4 x 24KB = 96KB per CTA).
// AMODE: 0 plain row-major A, 1 implicit im2col over attn (conv K=3 SAME)
// EPI:   0 fp32 | 1 fp16 split | 2 +bias,relu,fp16 split | 3 +bias fp32
// ---------------------------------------------------------------------------
#define TILE_T 8192             // 128 rows * 64B
#define STAGE_B (3 * TILE_T)    // 24576
#define NSTAGE 4

template <int AMODE, int EPI>
__global__ __launch_bounds__(128, 2)
void h16_gemm(const f16* __restrict__ Ah_, const f16* __restrict__ Al_,
              const f16* __restrict__ Bh_,
              const float* __restrict__ bias,
              float* __restrict__ Cf, f16* __restrict__ Ch, f16* __restrict__ Cl,
              int K, int lda, int ldb, int ldc,
              size_t sA, size_t sB, size_t sC)
{
    extern __shared__ char smem[];
    const uint32_t sbase = cvta_smem(smem);
    const int tid  = threadIdx.x;
    const int lane = tid & 31;
    const int wid  = tid >> 5;
    const int wm   = wid & 1;
    const int wn   = wid >> 1;

    const size_t z = blockIdx.z;
    Ah_ += z * sA; Al_ += z * sA;
    Bh_ += z * sB;
    if (Cf) Cf += z * sC;
    if (Ch) { Ch += z * sC; Cl += z * sC; }

    const int bm = blockIdx.y * 128;
    const int bn = blockIdx.x * 128;
    const int KT = K >> 5;

    float acc[4][8][4];
    #pragma unroll
    for (int a = 0; a < 4; ++a)
        #pragma unroll
        for (int b = 0; b < 8; ++b)
            #pragma unroll
            for (int c = 0; c < 4; ++c) acc[a][b][c] = 0.f;

    auto load_stage = [&](int slot, int kt) {
        const int k0 = kt * 32;
        const uint32_t sb = sbase + slot * STAGE_B;
        #pragma unroll
        for (int half = 0; half < 4; ++half) {
            const int idx = tid + half * 128;
            const int r = idx >> 2;
            const int c = idx & 3;
            const uint32_t so = sw64((uint32_t)(r * 64 + c * 16));
            if (AMODE == 0) {
                cpa16(sb + so,          Ah_ + (size_t)(bm + r) * lda + k0 + c * 8);
                cpa16(sb + TILE_T + so, Al_ + (size_t)(bm + r) * lda + k0 + c * 8);
            } else {
                const int tap = k0 >> 10;
                const int ccol = (k0 & 1023) + c * 8;
                const int m = bm + r;
                const int b = m >> 11;
                const int t = (m & 2047) + tap - 1;
                const unsigned ok = ((unsigned)t < 2048u) ? 16u : 0u;
                const size_t o = ((size_t)b * 2048 + (ok ? t : 0)) * 1024 + ccol;
                cpa16z(sb + so,          Ah_ + o, ok);
                cpa16z(sb + TILE_T + so, Al_ + o, ok);
            }
            cpa16(sb + 2 * TILE_T + so, Bh_ + (size_t)(bn + r) * ldb + k0 + c * 8);
        }
        cpa_commit();
    };

    auto compute_ks = [&](uint32_t sb, int ks) {
        const uint32_t sbB = sb + 2 * TILE_T;
        uint32_t Ahf[4][4], Alf[4][4];
        const int arow  = wm * 64 + (lane & 15);
        const int ahalf = lane >> 4;
        #pragma unroll
        for (int mf = 0; mf < 4; ++mf) {
            const uint32_t ao = sw64((uint32_t)((arow + mf * 16) * 64
                              + (ks * 2 + ahalf) * 16));
            LDM4(Ahf[mf], sb + ao);
            LDM4(Alf[mf], sb + TILE_T + ao);
        }
        const int bmat = lane >> 3;
        const int brow0 = wn * 64 + (lane & 7) + (bmat >> 1) * 8;
        const int bko = (ks * 2 + (bmat & 1)) * 16;
        #pragma unroll
        for (int np = 0; np < 4; ++np) {
            uint32_t Bhf[4];
            const uint32_t bo = sw64((uint32_t)((brow0 + np * 16) * 64 + bko));
            LDM4(Bhf, sbB + bo);
            // 2 terms, term-major across both n-subtiles: same-acc reuse = 8
            #pragma unroll
            for (int sub = 0; sub < 2; ++sub)
                #pragma unroll
                for (int mf = 0; mf < 4; ++mf)
                    MMA16816H(acc[mf][np * 2 + sub], Ahf[mf], &Bhf[sub * 2]);
            #pragma unroll
            for (int sub = 0; sub < 2; ++sub)
                #pragma unroll
                for (int mf = 0; mf < 4; ++mf)
                    MMA16816H(acc[mf][np * 2 + sub], Alf[mf], &Bhf[sub * 2]);
        }
    };

    load_stage(0, 0);
    load_stage(1, 1);
    load_stage(2, 2);

    for (int kt = 0; kt < KT; ++kt) {
        // groups issued after kt: min(KT-kt-1, 2). Force stage kt landed.
        if (kt + 3 <= KT) cpa_wait<2>();
        else if (kt + 2 == KT) cpa_wait<1>();
        else cpa_wait<0>();
        __syncthreads();   // all warps past iteration kt-1 reads; see stage kt
        const uint32_t sb = sbase + (kt % NSTAGE) * STAGE_B;
        compute_ks(sb, 0);
        if (kt + 3 < KT) load_stage((kt + 3) % NSTAGE, kt + 3);  // in MMA shadow
        compute_ks(sb, 1);
    }

    // ---- epilogue
    const int mrow = bm + wm * 64 + (lane >> 2);
    const int ncol = bn + wn * 64 + (lane & 3) * 2;
    #pragma unroll
    for (int mf = 0; mf < 4; ++mf) {
        #pragma unroll
        for (int nf = 0; nf < 8; ++nf) {
            const float* a4 = acc[mf][nf];
            #pragma unroll
            for (int h = 0; h < 2; ++h) {
                const int m = mrow + mf * 16 + h * 8;
                const int n = ncol + nf * 8;
                float v0 = a4[h * 2 + 0];
                float v1 = a4[h * 2 + 1];
                if (EPI == 0) {
                    *(float2*)(Cf + (size_t)m * ldc + n) = make_float2(v0, v1);
                } else if (EPI == 3) {
                    *(float2*)(Cf + (size_t)m * ldc + n) =
                        make_float2(v0 + bias[n], v1 + bias[n + 1]);
                } else {
                    if (EPI == 2) {
                        v0 = fmaxf(v0 + bias[n], 0.f);
                        v1 = fmaxf(v1 + bias[n + 1], 0.f);
                    }
                    f16 h0, l0, h1, l1;
                    hsplit(v0, h0, l0);
                    hsplit(v1, h1, l1);
                    __half2 vh, vl;
                    vh.x = h0; vh.y = h1;
                    vl.x = l0; vl.y = l1;
                    *(__half2*)(Ch + (size_t)m * ldc + n) = vh;
                    *(__half2*)(Cl + (size_t)m * ldc + n) = vl;
                }
            }
        }
    }
}

// ---------------------------------------------------------------------------
extern "C" void kernel_launch(void* const* d_in, const int* in_sizes, int n_in,
                              void* d_out, int out_size) {
    const int*   inputs     = (const int*)d_in[0];
    const int*   targets    = (const int*)d_in[1];
    const float* input_emb  = (const float*)d_in[2];
    const float* target_emb = (const float*)d_in[3];
    const float* conv_w     = (const float*)d_in[4];
    const float* conv_b     = (const float*)d_in[5];
    const float* dense_w    = (const float*)d_in[6];
    const float* dense_b    = (const float*)d_in[7];
    float* out = (float*)d_out;

    f16 *te_h, *te_l, *ie_h, *ieT, *p_h, *p_l, *at_h, *at_l, *hb_h, *hb_l, *cwh, *dwh;
    float* lg;
    cudaGetSymbolAddress((void**)&te_h, g_te_h);
    cudaGetSymbolAddress((void**)&te_l, g_te_l);
    cudaGetSymbolAddress((void**)&ie_h, g_ie_h);
    cudaGetSymbolAddress((void**)&ieT, g_ieT);
    cudaGetSymbolAddress((void**)&lg, g_logits);
    cudaGetSymbolAddress((void**)&p_h, g_p_h);
    cudaGetSymbolAddress((void**)&p_l, g_p_l);
    cudaGetSymbolAddress((void**)&at_h, g_at_h);
    cudaGetSymbolAddress((void**)&at_l, g_at_l);
    cudaGetSymbolAddress((void**)&hb_h, g_hb_h);
    cudaGetSymbolAddress((void**)&hb_l, g_hb_l);
    cudaGetSymbolAddress((void**)&cwh, g_cwh);
    cudaGetSymbolAddress((void**)&dwh, g_dwh);

    const int SMEMB = NSTAGE * STAGE_B;   // 98304 -> 2 CTAs/SM (192KB)
    cudaFuncSetAttribute(h16_gemm<0,0>, cudaFuncAttributeMaxDynamicSharedMemorySize, SMEMB);
    cudaFuncSetAttribute(h16_gemm<0,1>, cudaFuncAttributeMaxDynamicSharedMemorySize, SMEMB);
    cudaFuncSetAttribute(h16_gemm<1,2>, cudaFuncAttributeMaxDynamicSharedMemorySize, SMEMB);
    cudaFuncSetAttribute(h16_gemm<0,3>, cudaFuncAttributeMaxDynamicSharedMemorySize, SMEMB);

    // 1-2: gathers (te unscaled hi/lo; ie carries the 32 factor, hi only)
    gather_split16<<<NB * TT, 256>>>(targets, target_emb, te_h, te_l, NB * TT, 1.0f);
    gather_split16<<<NB * TI, 256>>>(inputs, input_emb, ie_h, nullptr, NB * TI, 32.0f);

    // 3: ieT = ie^T (hi only)
    transpose_h16<<<dim3(HH/32, TI/32, NB), dim3(32, 8)>>>(ie_h, ieT, TI, HH);

    // 4: logits = (te_h+te_l) @ ie_h^T   [B, TT, TI]   <-- PROFILED LAUNCH
    h16_gemm<0,0><<<dim3(TI/128, TT/128, NB), 128, SMEMB>>>(
        te_h, te_l, ie_h, nullptr, lg, nullptr, nullptr,
        HH, HH, HH, TI, (size_t)TT*HH, (size_t)TI*HH, (size_t)TT*TI);

    // 5-6: weight transposes (hi only)
    transpose_w16<<<dim3(UU/32, (3*HH)/32), dim3(32, 8)>>>(conv_w, cwh, 3*HH, UU);
    transpose_w16<<<dim3(HH/32, UU/32), dim3(32, 8)>>>(dense_w, dwh, UU, HH);

    // 7: softmax -> fp16 prob splits
    softmax_split16<<<NB * TT, 256>>>(lg, p_h, p_l);

    // 8: attn = (P_h+P_l) @ ieT^T   [B, TT, HH] -> fp16 splits
    h16_gemm<0,1><<<dim3(HH/128, TT/128, NB), 128, SMEMB>>>(
        p_h, p_l, ieT, nullptr, nullptr, at_h, at_l,
        TI, TI, TI, HH, (size_t)TT*TI, (size_t)HH*TI, (size_t)TT*HH);

    // 9: h = relu(conv1d(attn) + conv_b)   [8192, UU], im2col, fp16 splits out
    h16_gemm<1,2><<<dim3(UU/128, (NB*TT)/128, 1), 128, SMEMB>>>(
        at_h, at_l, cwh, conv_b, nullptr, hb_h, hb_l,
        3*HH, 0, 3*HH, UU, 0, 0, 0);

    // 10: out = (h_h+h_l) @ dense_w^T + dense_b   [8192, HH]
    h16_gemm<0,3><<<dim3(HH/128, (NB*TT)/128, 1), 128, SMEMB>>>(
        hb_h, hb_l, dwh, dense_b, out, nullptr, nullptr,
        UU, UU, UU, HH, 0, 0, 0);
}

// round 16
// speedup vs baseline: 2.3271x; 1.3193x over previous
#include <cuda_runtime.h>
#include <cuda_bf16.h>
#include <cuda_fp16.h>
#include <stdint.h>
#include <math.h>

#define NB 4
#define TT 2048
#define TI 2048
#define HH 1024
#define UU 4096

typedef __half f16;

// ---------------------------------------------------------------------------
// Scratch (allocation-free: __device__ globals), all fp16 operand planes
// ---------------------------------------------------------------------------
__device__ f16  g_te_h[(size_t)NB*TT*HH];
__device__ f16  g_te_l[(size_t)NB*TT*HH];
__device__ f16  g_ie_h[(size_t)NB*TI*HH];     // hi only (B operand of G1)
__device__ f16  g_ieT[(size_t)NB*HH*TI];      // hi only (B operand of G2)
__device__ float g_logits[(size_t)NB*TT*TI];
__device__ f16  g_p_h[(size_t)NB*TT*TI];
__device__ f16  g_p_l[(size_t)NB*TT*TI];
__device__ f16  g_at_h[(size_t)NB*TT*HH];     // attn hi only (G3 is 1-term)
__device__ f16  g_hb_h[(size_t)NB*TT*UU];
__device__ f16  g_hb_l[(size_t)NB*TT*UU];
__device__ f16  g_cwh[(size_t)UU*3*HH];       // conv weights fp16 hi only
__device__ f16  g_dwh[(size_t)HH*UU];         // dense weights fp16 hi only

// ---------------------------------------------------------------------------
// Helpers
// ---------------------------------------------------------------------------
__device__ __forceinline__ uint32_t cvta_smem(const void* p) {
    uint32_t a;
    asm("{ .reg .u64 t; cvta.to.shared.u64 t, %1; cvt.u32.u64 %0, t; }"
        : "=r"(a) : "l"(p));
    return a;
}
__device__ __forceinline__ void hsplit(float v, f16& h, f16& l) {
    h = __float2half(v);
    l = __float2half(v - __half2float(h));
}
__device__ __forceinline__ void cpa16(uint32_t d, const void* s) {
    asm volatile("cp.async.cg.shared.global [%0], [%1], 16;" :: "r"(d), "l"(s));
}
__device__ __forceinline__ void cpa16z(uint32_t d, const void* s, unsigned sz) {
    asm volatile("cp.async.cg.shared.global [%0], [%1], 16, %2;"
                 :: "r"(d), "l"(s), "r"(sz));
}
__device__ __forceinline__ void cpa_commit() {
    asm volatile("cp.async.commit_group;" ::: "memory");
}
template <int N>
__device__ __forceinline__ void cpa_wait() {
    asm volatile("cp.async.wait_group %0;" :: "n"(N) : "memory");
}
// SW64 swizzle: bits[4:5] ^= bits[7:8]
__device__ __forceinline__ uint32_t sw64(uint32_t o) {
    return o ^ ((o >> 3) & 0x30);
}

#define LDM4(f, a) \
    asm volatile("ldmatrix.sync.aligned.m8n8.x4.shared.b16 {%0,%1,%2,%3}, [%4];" \
        : "=r"((f)[0]), "=r"((f)[1]), "=r"((f)[2]), "=r"((f)[3]) : "r"(a))
#define MMA16816H(d, a, b) \
    asm volatile("mma.sync.aligned.m16n8k16.row.col.f32.f16.f16.f32 " \
        "{%0,%1,%2,%3}, {%4,%5,%6,%7}, {%8,%9}, {%0,%1,%2,%3};" \
        : "+f"((d)[0]), "+f"((d)[1]), "+f"((d)[2]), "+f"((d)[3]) \
        : "r"((a)[0]), "r"((a)[1]), "r"((a)[2]), "r"((a)[3]), \
          "r"((b)[0]), "r"((b)[1]))

// ---------------------------------------------------------------------------
// Embedding gather + scale + fp16 hi/lo split
// ---------------------------------------------------------------------------
__global__ void gather_split16(const int* __restrict__ idx, const float* __restrict__ emb,
                               f16* __restrict__ oh, f16* __restrict__ ol,
                               int n_tok, float scale) {
    int i = blockIdx.x * 256 + threadIdx.x;
    if (i >= n_tok * 256) return;
    int tok = i >> 8, h4 = i & 255;
    float4 v = ((const float4*)emb)[(size_t)idx[tok] * 256 + h4];
    float f[4] = {v.x * scale, v.y * scale, v.z * scale, v.w * scale};
    f16 h[4], l[4];
    #pragma unroll
    for (int k = 0; k < 4; ++k) hsplit(f[k], h[k], l[k]);
    size_t o = (size_t)tok * HH + h4 * 4;
    __half2 a, b;
    a.x = h[0]; a.y = h[1]; b.x = h[2]; b.y = h[3];
    *(__half2*)(oh + o) = a; *(__half2*)(oh + o + 2) = b;
    if (ol) {
        a.x = l[0]; a.y = l[1]; b.x = l[2]; b.y = l[3];
        *(__half2*)(ol + o) = a; *(__half2*)(ol + o + 2) = b;
    }
}

// ---------------------------------------------------------------------------
// fp16 transpose [R,C] -> [C,R], z batches
// ---------------------------------------------------------------------------
__global__ void transpose_h16(const f16* __restrict__ in, f16* __restrict__ out,
                              int R, int C) {
    __shared__ f16 t[32][33];
    in  += (size_t)blockIdx.z * R * C;
    out += (size_t)blockIdx.z * R * C;
    int c0 = blockIdx.x * 32, r0 = blockIdx.y * 32;
    for (int i = threadIdx.y; i < 32; i += 8)
        t[i][threadIdx.x] = in[(size_t)(r0 + i) * C + c0 + threadIdx.x];
    __syncthreads();
    for (int i = threadIdx.y; i < 32; i += 8)
        out[(size_t)(c0 + i) * R + r0 + threadIdx.x] = t[threadIdx.x][i];
}

// fp32 weight transpose [R,C] -> fp16 (hi only) [C,R]
__global__ void transpose_w16(const float* __restrict__ in,
                              f16* __restrict__ oh, int R, int C) {
    __shared__ float t[32][33];
    int c0 = blockIdx.x * 32, r0 = blockIdx.y * 32;
    for (int i = threadIdx.y; i < 32; i += 8)
        t[i][threadIdx.x] = in[(size_t)(r0 + i) * C + c0 + threadIdx.x];
    __syncthreads();
    for (int i = threadIdx.y; i < 32; i += 8)
        oh[(size_t)(c0 + i) * R + r0 + threadIdx.x] = __float2half(t[threadIdx.x][i]);
}

// ---------------------------------------------------------------------------
// Softmax over TI cols, writes fp16 hi/lo probabilities
// ---------------------------------------------------------------------------
__global__ void softmax_split16(const float* __restrict__ logits,
                                f16* __restrict__ ph_, f16* __restrict__ pl_) {
    __shared__ float red[256];
    const int tid = threadIdx.x;
    const float4* p = (const float4*)(logits + (size_t)blockIdx.x * TI);
    float4 v0 = p[tid];
    float4 v1 = p[tid + 256];

    float m = fmaxf(fmaxf(fmaxf(v0.x, v0.y), fmaxf(v0.z, v0.w)),
                    fmaxf(fmaxf(v1.x, v1.y), fmaxf(v1.z, v1.w)));
    red[tid] = m;
    __syncthreads();
    #pragma unroll
    for (int s = 128; s > 0; s >>= 1) {
        if (tid < s) red[tid] = fmaxf(red[tid], red[tid + s]);
        __syncthreads();
    }
    m = red[0];
    __syncthreads();

    v0.x = expf(v0.x - m); v0.y = expf(v0.y - m);
    v0.z = expf(v0.z - m); v0.w = expf(v0.w - m);
    v1.x = expf(v1.x - m); v1.y = expf(v1.y - m);
    v1.z = expf(v1.z - m); v1.w = expf(v1.w - m);

    red[tid] = v0.x + v0.y + v0.z + v0.w + v1.x + v1.y + v1.z + v1.w;
    __syncthreads();
    #pragma unroll
    for (int s = 128; s > 0; s >>= 1) {
        if (tid < s) red[tid] += red[tid + s];
        __syncthreads();
    }
    float inv = 1.f / red[0];

    size_t base = (size_t)blockIdx.x * TI;
    float f[8] = {v0.x*inv, v0.y*inv, v0.z*inv, v0.w*inv,
                  v1.x*inv, v1.y*inv, v1.z*inv, v1.w*inv};
    #pragma unroll
    for (int g = 0; g < 2; ++g) {
        size_t o = base + (size_t)(tid + g * 256) * 4;
        f16 h[4], l[4];
        #pragma unroll
        for (int k = 0; k < 4; ++k) hsplit(f[g*4 + k], h[k], l[k]);
        __half2 a, b;
        a.x = h[0]; a.y = h[1]; b.x = h[2]; b.y = h[3];
        *(__half2*)(ph_ + o) = a; *(__half2*)(ph_ + o + 2) = b;
        a.x = l[0]; a.y = l[1]; b.x = l[2]; b.y = l[3];
        *(__half2*)(pl_ + o) = a; *(__half2*)(pl_ + o + 2) = b;
    }
}

// ---------------------------------------------------------------------------
// Universal fp16 GEMM: C = (Ah [+ Al]) * Bh^T (+ epilogue).
// TERMS = 2: 2-term A split; TERMS = 1: hi-only A (conv).
// 128x128 CTA tile, 4 warps (64x64 warp tile), BK=32, SW64 smem,
// 4-stage cp.async pipeline, 2 CTAs/SM.
// Stage = TERMS*8KB (A) + 8KB (B).
// AMODE: 0 plain row-major A, 1 implicit im2col over attn (conv K=3 SAME)
// EPI:   0 fp32 | 1 fp16 hi only | 2 +bias,relu,fp16 split | 3 +bias fp32
// ---------------------------------------------------------------------------
#define TILE_T 8192             // 128 rows * 64B
#define NSTAGE 4

template <int AMODE, int EPI, int TERMS>
__global__ __launch_bounds__(128, 2)
void h16_gemm(const f16* __restrict__ Ah_, const f16* __restrict__ Al_,
              const f16* __restrict__ Bh_,
              const float* __restrict__ bias,
              float* __restrict__ Cf, f16* __restrict__ Ch, f16* __restrict__ Cl,
              int K, int lda, int ldb, int ldc,
              size_t sA, size_t sB, size_t sC)
{
    constexpr uint32_t ASZ = (uint32_t)TERMS * TILE_T;
    constexpr uint32_t SB_SZ = ASZ + TILE_T;

    extern __shared__ char smem[];
    const uint32_t sbase = cvta_smem(smem);
    const int tid  = threadIdx.x;
    const int lane = tid & 31;
    const int wid  = tid >> 5;
    const int wm   = wid & 1;
    const int wn   = wid >> 1;

    const size_t z = blockIdx.z;
    Ah_ += z * sA;
    if (TERMS == 2) Al_ += z * sA;
    Bh_ += z * sB;
    if (Cf) Cf += z * sC;
    if (Ch) { Ch += z * sC; if (Cl) Cl += z * sC; }

    const int bm = blockIdx.y * 128;
    const int bn = blockIdx.x * 128;
    const int KT = K >> 5;

    float acc[4][8][4];
    #pragma unroll
    for (int a = 0; a < 4; ++a)
        #pragma unroll
        for (int b = 0; b < 8; ++b)
            #pragma unroll
            for (int c = 0; c < 4; ++c) acc[a][b][c] = 0.f;

    auto load_stage = [&](int slot, int kt) {
        const int k0 = kt * 32;
        const uint32_t sb = sbase + slot * SB_SZ;
        #pragma unroll
        for (int half = 0; half < 4; ++half) {
            const int idx = tid + half * 128;
            const int r = idx >> 2;
            const int c = idx & 3;
            const uint32_t so = sw64((uint32_t)(r * 64 + c * 16));
            if (AMODE == 0) {
                cpa16(sb + so, Ah_ + (size_t)(bm + r) * lda + k0 + c * 8);
                if (TERMS == 2)
                    cpa16(sb + TILE_T + so, Al_ + (size_t)(bm + r) * lda + k0 + c * 8);
            } else {
                const int tap = k0 >> 10;
                const int ccol = (k0 & 1023) + c * 8;
                const int m = bm + r;
                const int b = m >> 11;
                const int t = (m & 2047) + tap - 1;
                const unsigned ok = ((unsigned)t < 2048u) ? 16u : 0u;
                const size_t o = ((size_t)b * 2048 + (ok ? t : 0)) * 1024 + ccol;
                cpa16z(sb + so, Ah_ + o, ok);
                if (TERMS == 2)
                    cpa16z(sb + TILE_T + so, Al_ + o, ok);
            }
            cpa16(sb + ASZ + so, Bh_ + (size_t)(bn + r) * ldb + k0 + c * 8);
        }
        cpa_commit();
    };

    auto compute_ks = [&](uint32_t sb, int ks) {
        const uint32_t sbB = sb + ASZ;
        uint32_t Ahf[4][4], Alf[4][4];
        const int arow  = wm * 64 + (lane & 15);
        const int ahalf = lane >> 4;
        #pragma unroll
        for (int mf = 0; mf < 4; ++mf) {
            const uint32_t ao = sw64((uint32_t)((arow + mf * 16) * 64
                              + (ks * 2 + ahalf) * 16));
            LDM4(Ahf[mf], sb + ao);
            if (TERMS == 2) LDM4(Alf[mf], sb + TILE_T + ao);
        }
        const int bmat = lane >> 3;
        const int brow0 = wn * 64 + (lane & 7) + (bmat >> 1) * 8;
        const int bko = (ks * 2 + (bmat & 1)) * 16;
        #pragma unroll
        for (int np = 0; np < 4; ++np) {
            uint32_t Bhf[4];
            const uint32_t bo = sw64((uint32_t)((brow0 + np * 16) * 64 + bko));
            LDM4(Bhf, sbB + bo);
            #pragma unroll
            for (int sub = 0; sub < 2; ++sub)
                #pragma unroll
                for (int mf = 0; mf < 4; ++mf)
                    MMA16816H(acc[mf][np * 2 + sub], Ahf[mf], &Bhf[sub * 2]);
            if (TERMS == 2) {
                #pragma unroll
                for (int sub = 0; sub < 2; ++sub)
                    #pragma unroll
                    for (int mf = 0; mf < 4; ++mf)
                        MMA16816H(acc[mf][np * 2 + sub], Alf[mf], &Bhf[sub * 2]);
            }
        }
    };

    load_stage(0, 0);
    load_stage(1, 1);
    load_stage(2, 2);

    for (int kt = 0; kt < KT; ++kt) {
        // groups issued after kt: min(KT-kt-1, 2). Force stage kt landed.
        if (kt + 3 <= KT) cpa_wait<2>();
        else if (kt + 2 == KT) cpa_wait<1>();
        else cpa_wait<0>();
        __syncthreads();
        const uint32_t sb = sbase + (kt % NSTAGE) * SB_SZ;
        compute_ks(sb, 0);
        if (kt + 3 < KT) load_stage((kt + 3) % NSTAGE, kt + 3);
        compute_ks(sb, 1);
    }

    // ---- epilogue
    const int mrow = bm + wm * 64 + (lane >> 2);
    const int ncol = bn + wn * 64 + (lane & 3) * 2;
    #pragma unroll
    for (int mf = 0; mf < 4; ++mf) {
        #pragma unroll
        for (int nf = 0; nf < 8; ++nf) {
            const float* a4 = acc[mf][nf];
            #pragma unroll
            for (int h = 0; h < 2; ++h) {
                const int m = mrow + mf * 16 + h * 8;
                const int n = ncol + nf * 8;
                float v0 = a4[h * 2 + 0];
                float v1 = a4[h * 2 + 1];
                if (EPI == 0) {
                    *(float2*)(Cf + (size_t)m * ldc + n) = make_float2(v0, v1);
                } else if (EPI == 3) {
                    *(float2*)(Cf + (size_t)m * ldc + n) =
                        make_float2(v0 + bias[n], v1 + bias[n + 1]);
                } else if (EPI == 1) {
                    __half2 vh;
                    vh.x = __float2half(v0);
                    vh.y = __float2half(v1);
                    *(__half2*)(Ch + (size_t)m * ldc + n) = vh;
                } else {
                    v0 = fmaxf(v0 + bias[n], 0.f);
                    v1 = fmaxf(v1 + bias[n + 1], 0.f);
                    f16 h0, l0, h1, l1;
                    hsplit(v0, h0, l0);
                    hsplit(v1, h1, l1);
                    __half2 vh, vl;
                    vh.x = h0; vh.y = h1;
                    vl.x = l0; vl.y = l1;
                    *(__half2*)(Ch + (size_t)m * ldc + n) = vh;
                    *(__half2*)(Cl + (size_t)m * ldc + n) = vl;
                }
            }
        }
    }
}

// ---------------------------------------------------------------------------
extern "C" void kernel_launch(void* const* d_in, const int* in_sizes, int n_in,
                              void* d_out, int out_size) {
    const int*   inputs     = (const int*)d_in[0];
    const int*   targets    = (const int*)d_in[1];
    const float* input_emb  = (const float*)d_in[2];
    const float* target_emb = (const float*)d_in[3];
    const float* conv_w     = (const float*)d_in[4];
    const float* conv_b     = (const float*)d_in[5];
    const float* dense_w    = (const float*)d_in[6];
    const float* dense_b    = (const float*)d_in[7];
    float* out = (float*)d_out;

    f16 *te_h, *te_l, *ie_h, *ieT, *p_h, *p_l, *at_h, *hb_h, *hb_l, *cwh, *dwh;
    float* lg;
    cudaGetSymbolAddress((void**)&te_h, g_te_h);
    cudaGetSymbolAddress((void**)&te_l, g_te_l);
    cudaGetSymbolAddress((void**)&ie_h, g_ie_h);
    cudaGetSymbolAddress((void**)&ieT, g_ieT);
    cudaGetSymbolAddress((void**)&lg, g_logits);
    cudaGetSymbolAddress((void**)&p_h, g_p_h);
    cudaGetSymbolAddress((void**)&p_l, g_p_l);
    cudaGetSymbolAddress((void**)&at_h, g_at_h);
    cudaGetSymbolAddress((void**)&hb_h, g_hb_h);
    cudaGetSymbolAddress((void**)&hb_l, g_hb_l);
    cudaGetSymbolAddress((void**)&cwh, g_cwh);
    cudaGetSymbolAddress((void**)&dwh, g_dwh);

    const int SMEMB2 = NSTAGE * 3 * TILE_T;  // 98304 (2-term)
    const int SMEMB1 = NSTAGE * 2 * TILE_T;  // 65536 (1-term)
    cudaFuncSetAttribute(h16_gemm<0,0,2>, cudaFuncAttributeMaxDynamicSharedMemorySize, SMEMB2);
    cudaFuncSetAttribute(h16_gemm<0,1,2>, cudaFuncAttributeMaxDynamicSharedMemorySize, SMEMB2);
    cudaFuncSetAttribute(h16_gemm<1,2,1>, cudaFuncAttributeMaxDynamicSharedMemorySize, SMEMB1);
    cudaFuncSetAttribute(h16_gemm<0,3,2>, cudaFuncAttributeMaxDynamicSharedMemorySize, SMEMB2);

    // 1-2: gathers (te unscaled hi/lo; ie carries the 32 factor, hi only)
    gather_split16<<<NB * TT, 256>>>(targets, target_emb, te_h, te_l, NB * TT, 1.0f);
    gather_split16<<<NB * TI, 256>>>(inputs, input_emb, ie_h, nullptr, NB * TI, 32.0f);

    // 3: ieT = ie^T (hi only)
    transpose_h16<<<dim3(HH/32, TI/32, NB), dim3(32, 8)>>>(ie_h, ieT, TI, HH);

    // 4: logits = (te_h+te_l) @ ie_h^T   [B, TT, TI]   <-- PROFILED LAUNCH
    h16_gemm<0,0,2><<<dim3(TI/128, TT/128, NB), 128, SMEMB2>>>(
        te_h, te_l, ie_h, nullptr, lg, nullptr, nullptr,
        HH, HH, HH, TI, (size_t)TT*HH, (size_t)TI*HH, (size_t)TT*TI);

    // 5-6: weight transposes (hi only)
    transpose_w16<<<dim3(UU/32, (3*HH)/32), dim3(32, 8)>>>(conv_w, cwh, 3*HH, UU);
    transpose_w16<<<dim3(HH/32, UU/32), dim3(32, 8)>>>(dense_w, dwh, UU, HH);

    // 7: softmax -> fp16 prob splits
    softmax_split16<<<NB * TT, 256>>>(lg, p_h, p_l);

    // 8: attn = (P_h+P_l) @ ieT^T   [B, TT, HH] -> fp16 hi only
    h16_gemm<0,1,2><<<dim3(HH/128, TT/128, NB), 128, SMEMB2>>>(
        p_h, p_l, ieT, nullptr, nullptr, at_h, nullptr,
        TI, TI, TI, HH, (size_t)TT*TI, (size_t)HH*TI, (size_t)TT*HH);

    // 9: h = relu(conv1d(attn) + conv_b)   [8192, UU], 1-term im2col GEMM
    h16_gemm<1,2,1><<<dim3(UU/128, (NB*TT)/128, 1), 128, SMEMB1>>>(
        at_h, nullptr, cwh, conv_b, nullptr, hb_h, hb_l,
        3*HH, 0, 3*HH, UU, 0, 0, 0);

    // 10: out = (h_h+h_l) @ dense_w^T + dense_b   [8192, HH], 2-term
    h16_gemm<0,3,2><<<dim3(HH/128, (NB*TT)/128, 1), 128, SMEMB2>>>(
        hb_h, hb_l, dwh, dense_b, out, nullptr, nullptr,
        UU, UU, UU, HH, 0, 0, 0);
}

// round 17
// speedup vs baseline: 2.8824x; 1.2386x over previous
#include <cuda_runtime.h>
#include <cuda_bf16.h>
#include <cuda_fp16.h>
#include <stdint.h>
#include <math.h>

#define NB 4
#define TT 2048
#define TI 2048
#define HH 1024
#define UU 4096

typedef __half f16;

// ---------------------------------------------------------------------------
// Scratch (allocation-free: __device__ globals)
// ---------------------------------------------------------------------------
__device__ f16  g_te_h[(size_t)NB*TT*HH];
__device__ f16  g_te_l[(size_t)NB*TT*HH];
__device__ f16  g_ie_h[(size_t)NB*TI*HH];     // hi only (B operand of G1)
__device__ f16  g_ieT[(size_t)NB*HH*TI];      // hi only (B operand of G2)
__device__ float g_logits[(size_t)NB*TT*TI];
__device__ f16  g_p_h[(size_t)NB*TT*TI];      // probs hi only (G2 1-term)
__device__ f16  g_at_h[(size_t)NB*TT*HH];     // attn hi only (G3 1-term)
__device__ f16  g_hb_h[(size_t)NB*TT*UU];     // conv out hi only (G4 1-term)
__device__ f16  g_cwh[(size_t)UU*3*HH];       // conv weights fp16 hi only
__device__ f16  g_dwh[(size_t)HH*UU];         // dense weights fp16 hi only

// ---------------------------------------------------------------------------
// Helpers
// ---------------------------------------------------------------------------
__device__ __forceinline__ uint32_t cvta_smem(const void* p) {
    uint32_t a;
    asm("{ .reg .u64 t; cvta.to.shared.u64 t, %1; cvt.u32.u64 %0, t; }"
        : "=r"(a) : "l"(p));
    return a;
}
__device__ __forceinline__ void hsplit(float v, f16& h, f16& l) {
    h = __float2half(v);
    l = __float2half(v - __half2float(h));
}
__device__ __forceinline__ void cpa16(uint32_t d, const void* s) {
    asm volatile("cp.async.cg.shared.global [%0], [%1], 16;" :: "r"(d), "l"(s));
}
__device__ __forceinline__ void cpa16z(uint32_t d, const void* s, unsigned sz) {
    asm volatile("cp.async.cg.shared.global [%0], [%1], 16, %2;"
                 :: "r"(d), "l"(s), "r"(sz));
}
__device__ __forceinline__ void cpa_commit() {
    asm volatile("cp.async.commit_group;" ::: "memory");
}
template <int N>
__device__ __forceinline__ void cpa_wait() {
    asm volatile("cp.async.wait_group %0;" :: "n"(N) : "memory");
}
// SW64 swizzle: bits[4:5] ^= bits[7:8]
__device__ __forceinline__ uint32_t sw64(uint32_t o) {
    return o ^ ((o >> 3) & 0x30);
}

#define LDM4(f, a) \
    asm volatile("ldmatrix.sync.aligned.m8n8.x4.shared.b16 {%0,%1,%2,%3}, [%4];" \
        : "=r"((f)[0]), "=r"((f)[1]), "=r"((f)[2]), "=r"((f)[3]) : "r"(a))
#define MMA16816H(d, a, b) \
    asm volatile("mma.sync.aligned.m16n8k16.row.col.f32.f16.f16.f32 " \
        "{%0,%1,%2,%3}, {%4,%5,%6,%7}, {%8,%9}, {%0,%1,%2,%3};" \
        : "+f"((d)[0]), "+f"((d)[1]), "+f"((d)[2]), "+f"((d)[3]) \
        : "r"((a)[0]), "r"((a)[1]), "r"((a)[2]), "r"((a)[3]), \
          "r"((b)[0]), "r"((b)[1]))

// ---------------------------------------------------------------------------
// Embedding gather + scale + fp16 hi/lo split
// ---------------------------------------------------------------------------
__global__ void gather_split16(const int* __restrict__ idx, const float* __restrict__ emb,
                               f16* __restrict__ oh, f16* __restrict__ ol,
                               int n_tok, float scale) {
    int i = blockIdx.x * 256 + threadIdx.x;
    if (i >= n_tok * 256) return;
    int tok = i >> 8, h4 = i & 255;
    float4 v = ((const float4*)emb)[(size_t)idx[tok] * 256 + h4];
    float f[4] = {v.x * scale, v.y * scale, v.z * scale, v.w * scale};
    f16 h[4], l[4];
    #pragma unroll
    for (int k = 0; k < 4; ++k) hsplit(f[k], h[k], l[k]);
    size_t o = (size_t)tok * HH + h4 * 4;
    __half2 a, b;
    a.x = h[0]; a.y = h[1]; b.x = h[2]; b.y = h[3];
    *(__half2*)(oh + o) = a; *(__half2*)(oh + o + 2) = b;
    if (ol) {
        a.x = l[0]; a.y = l[1]; b.x = l[2]; b.y = l[3];
        *(__half2*)(ol + o) = a; *(__half2*)(ol + o + 2) = b;
    }
}

// ---------------------------------------------------------------------------
// fp16 transpose [R,C] -> [C,R], z batches
// ---------------------------------------------------------------------------
__global__ void transpose_h16(const f16* __restrict__ in, f16* __restrict__ out,
                              int R, int C) {
    __shared__ f16 t[32][33];
    in  += (size_t)blockIdx.z * R * C;
    out += (size_t)blockIdx.z * R * C;
    int c0 = blockIdx.x * 32, r0 = blockIdx.y * 32;
    for (int i = threadIdx.y; i < 32; i += 8)
        t[i][threadIdx.x] = in[(size_t)(r0 + i) * C + c0 + threadIdx.x];
    __syncthreads();
    for (int i = threadIdx.y; i < 32; i += 8)
        out[(size_t)(c0 + i) * R + r0 + threadIdx.x] = t[threadIdx.x][i];
}

// fp32 weight transpose [R,C] -> fp16 (hi only) [C,R]
__global__ void transpose_w16(const float* __restrict__ in,
                              f16* __restrict__ oh, int R, int C) {
    __shared__ float t[32][33];
    int c0 = blockIdx.x * 32, r0 = blockIdx.y * 32;
    for (int i = threadIdx.y; i < 32; i += 8)
        t[i][threadIdx.x] = in[(size_t)(r0 + i) * C + c0 + threadIdx.x];
    __syncthreads();
    for (int i = threadIdx.y; i < 32; i += 8)
        oh[(size_t)(c0 + i) * R + r0 + threadIdx.x] = __float2half(t[threadIdx.x][i]);
}

// ---------------------------------------------------------------------------
// Softmax over TI cols, writes fp16 hi probabilities only
// ---------------------------------------------------------------------------
__global__ void softmax16(const float* __restrict__ logits,
                          f16* __restrict__ ph_) {
    __shared__ float red[256];
    const int tid = threadIdx.x;
    const float4* p = (const float4*)(logits + (size_t)blockIdx.x * TI);
    float4 v0 = p[tid];
    float4 v1 = p[tid + 256];

    float m = fmaxf(fmaxf(fmaxf(v0.x, v0.y), fmaxf(v0.z, v0.w)),
                    fmaxf(fmaxf(v1.x, v1.y), fmaxf(v1.z, v1.w)));
    red[tid] = m;
    __syncthreads();
    #pragma unroll
    for (int s = 128; s > 0; s >>= 1) {
        if (tid < s) red[tid] = fmaxf(red[tid], red[tid + s]);
        __syncthreads();
    }
    m = red[0];
    __syncthreads();

    v0.x = expf(v0.x - m); v0.y = expf(v0.y - m);
    v0.z = expf(v0.z - m); v0.w = expf(v0.w - m);
    v1.x = expf(v1.x - m); v1.y = expf(v1.y - m);
    v1.z = expf(v1.z - m); v1.w = expf(v1.w - m);

    red[tid] = v0.x + v0.y + v0.z + v0.w + v1.x + v1.y + v1.z + v1.w;
    __syncthreads();
    #pragma unroll
    for (int s = 128; s > 0; s >>= 1) {
        if (tid < s) red[tid] += red[tid + s];
        __syncthreads();
    }
    float inv = 1.f / red[0];

    size_t base = (size_t)blockIdx.x * TI;
    float f[8] = {v0.x*inv, v0.y*inv, v0.z*inv, v0.w*inv,
                  v1.x*inv, v1.y*inv, v1.z*inv, v1.w*inv};
    #pragma unroll
    for (int g = 0; g < 2; ++g) {
        size_t o = base + (size_t)(tid + g * 256) * 4;
        __half2 a, b;
        a.x = __float2half(f[g*4 + 0]); a.y = __float2half(f[g*4 + 1]);
        b.x = __float2half(f[g*4 + 2]); b.y = __float2half(f[g*4 + 3]);
        *(__half2*)(ph_ + o) = a; *(__half2*)(ph_ + o + 2) = b;
    }
}

// ---------------------------------------------------------------------------
// Universal fp16 GEMM: C = (Ah [+ Al]) * Bh^T (+ epilogue).
// TERMS = 2: 2-term A split; TERMS = 1: hi-only A.
// 128x128 CTA tile, 4 warps (64x64 warp tile), BK=32, SW64 smem,
// 4-stage cp.async pipeline, 2 CTAs/SM.
// AMODE: 0 plain row-major A, 1 implicit im2col over attn (conv K=3 SAME)
// EPI:   0 fp32 | 1 fp16 hi | 2 +bias,relu,fp16 hi | 3 +bias fp32
// ---------------------------------------------------------------------------
#define TILE_T 8192             // 128 rows * 64B
#define NSTAGE 4

template <int AMODE, int EPI, int TERMS>
__global__ __launch_bounds__(128, 2)
void h16_gemm(const f16* __restrict__ Ah_, const f16* __restrict__ Al_,
              const f16* __restrict__ Bh_,
              const float* __restrict__ bias,
              float* __restrict__ Cf, f16* __restrict__ Ch,
              int K, int lda, int ldb, int ldc,
              size_t sA, size_t sB, size_t sC)
{
    constexpr uint32_t ASZ = (uint32_t)TERMS * TILE_T;
    constexpr uint32_t SB_SZ = ASZ + TILE_T;

    extern __shared__ char smem[];
    const uint32_t sbase = cvta_smem(smem);
    const int tid  = threadIdx.x;
    const int lane = tid & 31;
    const int wid  = tid >> 5;
    const int wm   = wid & 1;
    const int wn   = wid >> 1;

    const size_t z = blockIdx.z;
    Ah_ += z * sA;
    if (TERMS == 2) Al_ += z * sA;
    Bh_ += z * sB;
    if (Cf) Cf += z * sC;
    if (Ch) Ch += z * sC;

    const int bm = blockIdx.y * 128;
    const int bn = blockIdx.x * 128;
    const int KT = K >> 5;

    float acc[4][8][4];
    #pragma unroll
    for (int a = 0; a < 4; ++a)
        #pragma unroll
        for (int b = 0; b < 8; ++b)
            #pragma unroll
            for (int c = 0; c < 4; ++c) acc[a][b][c] = 0.f;

    auto load_stage = [&](int slot, int kt) {
        const int k0 = kt * 32;
        const uint32_t sb = sbase + slot * SB_SZ;
        #pragma unroll
        for (int half = 0; half < 4; ++half) {
            const int idx = tid + half * 128;
            const int r = idx >> 2;
            const int c = idx & 3;
            const uint32_t so = sw64((uint32_t)(r * 64 + c * 16));
            if (AMODE == 0) {
                cpa16(sb + so, Ah_ + (size_t)(bm + r) * lda + k0 + c * 8);
                if (TERMS == 2)
                    cpa16(sb + TILE_T + so, Al_ + (size_t)(bm + r) * lda + k0 + c * 8);
            } else {
                const int tap = k0 >> 10;
                const int ccol = (k0 & 1023) + c * 8;
                const int m = bm + r;
                const int b = m >> 11;
                const int t = (m & 2047) + tap - 1;
                const unsigned ok = ((unsigned)t < 2048u) ? 16u : 0u;
                const size_t o = ((size_t)b * 2048 + (ok ? t : 0)) * 1024 + ccol;
                cpa16z(sb + so, Ah_ + o, ok);
                if (TERMS == 2)
                    cpa16z(sb + TILE_T + so, Al_ + o, ok);
            }
            cpa16(sb + ASZ + so, Bh_ + (size_t)(bn + r) * ldb + k0 + c * 8);
        }
        cpa_commit();
    };

    auto compute_ks = [&](uint32_t sb, int ks) {
        const uint32_t sbB = sb + ASZ;
        uint32_t Ahf[4][4], Alf[4][4];
        const int arow  = wm * 64 + (lane & 15);
        const int ahalf = lane >> 4;
        #pragma unroll
        for (int mf = 0; mf < 4; ++mf) {
            const uint32_t ao = sw64((uint32_t)((arow + mf * 16) * 64
                              + (ks * 2 + ahalf) * 16));
            LDM4(Ahf[mf], sb + ao);
            if (TERMS == 2) LDM4(Alf[mf], sb + TILE_T + ao);
        }
        const int bmat = lane >> 3;
        const int brow0 = wn * 64 + (lane & 7) + (bmat >> 1) * 8;
        const int bko = (ks * 2 + (bmat & 1)) * 16;
        #pragma unroll
        for (int np = 0; np < 4; ++np) {
            uint32_t Bhf[4];
            const uint32_t bo = sw64((uint32_t)((brow0 + np * 16) * 64 + bko));
            LDM4(Bhf, sbB + bo);
            #pragma unroll
            for (int sub = 0; sub < 2; ++sub)
                #pragma unroll
                for (int mf = 0; mf < 4; ++mf)
                    MMA16816H(acc[mf][np * 2 + sub], Ahf[mf], &Bhf[sub * 2]);
            if (TERMS == 2) {
                #pragma unroll
                for (int sub = 0; sub < 2; ++sub)
                    #pragma unroll
                    for (int mf = 0; mf < 4; ++mf)
                        MMA16816H(acc[mf][np * 2 + sub], Alf[mf], &Bhf[sub * 2]);
            }
        }
    };

    load_stage(0, 0);
    load_stage(1, 1);
    load_stage(2, 2);

    for (int kt = 0; kt < KT; ++kt) {
        if (kt + 3 <= KT) cpa_wait<2>();
        else if (kt + 2 == KT) cpa_wait<1>();
        else cpa_wait<0>();
        __syncthreads();
        const uint32_t sb = sbase + (kt % NSTAGE) * SB_SZ;
        compute_ks(sb, 0);
        if (kt + 3 < KT) load_stage((kt + 3) % NSTAGE, kt + 3);
        compute_ks(sb, 1);
    }

    // ---- epilogue
    const int mrow = bm + wm * 64 + (lane >> 2);
    const int ncol = bn + wn * 64 + (lane & 3) * 2;
    #pragma unroll
    for (int mf = 0; mf < 4; ++mf) {
        #pragma unroll
        for (int nf = 0; nf < 8; ++nf) {
            const float* a4 = acc[mf][nf];
            #pragma unroll
            for (int h = 0; h < 2; ++h) {
                const int m = mrow + mf * 16 + h * 8;
                const int n = ncol + nf * 8;
                float v0 = a4[h * 2 + 0];
                float v1 = a4[h * 2 + 1];
                if (EPI == 0) {
                    *(float2*)(Cf + (size_t)m * ldc + n) = make_float2(v0, v1);
                } else if (EPI == 3) {
                    *(float2*)(Cf + (size_t)m * ldc + n) =
                        make_float2(v0 + bias[n], v1 + bias[n + 1]);
                } else {
                    if (EPI == 2) {
                        v0 = fmaxf(v0 + bias[n], 0.f);
                        v1 = fmaxf(v1 + bias[n + 1], 0.f);
                    }
                    __half2 vh;
                    vh.x = __float2half(v0);
                    vh.y = __float2half(v1);
                    *(__half2*)(Ch + (size_t)m * ldc + n) = vh;
                }
            }
        }
    }
}

// ---------------------------------------------------------------------------
extern "C" void kernel_launch(void* const* d_in, const int* in_sizes, int n_in,
                              void* d_out, int out_size) {
    const int*   inputs     = (const int*)d_in[0];
    const int*   targets    = (const int*)d_in[1];
    const float* input_emb  = (const float*)d_in[2];
    const float* target_emb = (const float*)d_in[3];
    const float* conv_w     = (const float*)d_in[4];
    const float* conv_b     = (const float*)d_in[5];
    const float* dense_w    = (const float*)d_in[6];
    const float* dense_b    = (const float*)d_in[7];
    float* out = (float*)d_out;

    f16 *te_h, *te_l, *ie_h, *ieT, *p_h, *at_h, *hb_h, *cwh, *dwh;
    float* lg;
    cudaGetSymbolAddress((void**)&te_h, g_te_h);
    cudaGetSymbolAddress((void**)&te_l, g_te_l);
    cudaGetSymbolAddress((void**)&ie_h, g_ie_h);
    cudaGetSymbolAddress((void**)&ieT, g_ieT);
    cudaGetSymbolAddress((void**)&lg, g_logits);
    cudaGetSymbolAddress((void**)&p_h, g_p_h);
    cudaGetSymbolAddress((void**)&at_h, g_at_h);
    cudaGetSymbolAddress((void**)&hb_h, g_hb_h);
    cudaGetSymbolAddress((void**)&cwh, g_cwh);
    cudaGetSymbolAddress((void**)&dwh, g_dwh);

    const int SMEMB2 = NSTAGE * 3 * TILE_T;  // 98304 (2-term)
    const int SMEMB1 = NSTAGE * 2 * TILE_T;  // 65536 (1-term)
    cudaFuncSetAttribute(h16_gemm<0,0,2>, cudaFuncAttributeMaxDynamicSharedMemorySize, SMEMB2);
    cudaFuncSetAttribute(h16_gemm<0,1,1>, cudaFuncAttributeMaxDynamicSharedMemorySize, SMEMB1);
    cudaFuncSetAttribute(h16_gemm<1,2,1>, cudaFuncAttributeMaxDynamicSharedMemorySize, SMEMB1);
    cudaFuncSetAttribute(h16_gemm<0,3,1>, cudaFuncAttributeMaxDynamicSharedMemorySize, SMEMB1);

    // 1-2: gathers (te hi/lo for 2-term G1; ie hi only, carries the 32 factor)
    gather_split16<<<NB * TT, 256>>>(targets, target_emb, te_h, te_l, NB * TT, 1.0f);
    gather_split16<<<NB * TI, 256>>>(inputs, input_emb, ie_h, nullptr, NB * TI, 32.0f);

    // 3: ieT = ie^T (hi only)
    transpose_h16<<<dim3(HH/32, TI/32, NB), dim3(32, 8)>>>(ie_h, ieT, TI, HH);

    // 4: logits = (te_h+te_l) @ ie_h^T   [B, TT, TI]   <-- PROFILED LAUNCH
    h16_gemm<0,0,2><<<dim3(TI/128, TT/128, NB), 128, SMEMB2>>>(
        te_h, te_l, ie_h, nullptr, lg, nullptr,
        HH, HH, HH, TI, (size_t)TT*HH, (size_t)TI*HH, (size_t)TT*TI);

    // 5-6: weight transposes (hi only)
    transpose_w16<<<dim3(UU/32, (3*HH)/32), dim3(32, 8)>>>(conv_w, cwh, 3*HH, UU);
    transpose_w16<<<dim3(HH/32, UU/32), dim3(32, 8)>>>(dense_w, dwh, UU, HH);

    // 7: softmax -> fp16 probs (hi only)
    softmax16<<<NB * TT, 256>>>(lg, p_h);

    // 8: attn = P_h @ ieT^T   [B, TT, HH] -> fp16 hi, 1-term
    h16_gemm<0,1,1><<<dim3(HH/128, TT/128, NB), 128, SMEMB1>>>(
        p_h, nullptr, ieT, nullptr, nullptr, at_h,
        TI, TI, TI, HH, (size_t)TT*TI, (size_t)HH*TI, (size_t)TT*HH);

    // 9: h = relu(conv1d(attn) + conv_b)   [8192, UU], 1-term im2col GEMM
    h16_gemm<1,2,1><<<dim3(UU/128, (NB*TT)/128, 1), 128, SMEMB1>>>(
        at_h, nullptr, cwh, conv_b, nullptr, hb_h,
        3*HH, 0, 3*HH, UU, 0, 0, 0);

    // 10: out = h_h @ dense_w^T + dense_b   [8192, HH], 1-term
    h16_gemm<0,3,1><<<dim3(HH/128, (NB*TT)/128, 1), 128, SMEMB1>>>(
        hb_h, nullptr, dwh, dense_b, out, nullptr,
        UU, UU, UU, HH, 0, 0, 0);
}